// round 6
// baseline (speedup 1.0000x reference)
#include <cuda_runtime.h>
#include <cuda_fp16.h>
#include <math.h>

#define NN 50000
#define EE 600000
#define DD 128
#define GG 8

// ---------------- scratch (device globals: no allocation allowed) ----------------
__device__ float d_agg[NN * DD];
__device__ float d_f[NN * DD];
__device__ int   d_deg[NN];
__device__ int   d_start[NN];
__device__ int   d_cur[NN];
__device__ int   d_adj[EE];
__device__ float d_invdeg[NN];
__device__ float d_gsum[GG * DD];
__device__ float d_gsumsq[GG * DD];
__device__ int   d_cnt[GG];
__device__ float d_An[GG * DD];
__device__ float d_Bn[GG * DD];
__device__ uint2 d_Wpk[8192];   // fp16 packed W fragments: [(op*8+c)*128 + d]*4 + q4

// ---------------- prep: zero scratch + pack weights to fp16 fragment layout ----------------
__global__ void k_prep(const float* __restrict__ Wl, const float* __restrict__ Wr, int n) {
    int i = blockIdx.x * blockDim.x + threadIdx.x;
    if (i < n) d_deg[i] = 0;
    if (i < GG * DD) { d_gsum[i] = 0.f; d_gsumsq[i] = 0.f; }
    if (i < GG) d_cnt[i] = 0;
    if (i < 8192) {
        int q4 = i & 3, d = (i >> 2) & 127, c = (i >> 9) & 7, op = i >> 12;
        const float* W = op ? Wr : Wl;
        int k0 = c * 16;
        float2 p0 = *(const float2*)(W + (size_t)d * DD + k0 + q4 * 2);
        float2 p1 = *(const float2*)(W + (size_t)d * DD + k0 + 8 + q4 * 2);
        __half2 h0 = __float22half2_rn(p0);
        __half2 h1 = __float22half2_rn(p1);
        uint2 o;
        o.x = *reinterpret_cast<unsigned*>(&h0);
        o.y = *reinterpret_cast<unsigned*>(&h1);
        d_Wpk[i] = o;
    }
}

// ---------------- histogram of dst degrees + per-graph node counts ----------------
__global__ void k_hist(const int* __restrict__ ei, const int* __restrict__ batch, int e, int n) {
    int i = blockIdx.x * blockDim.x + threadIdx.x;
    if (i < e) atomicAdd(&d_deg[ei[e + i]], 1);
    int key = (i < n) ? batch[i] : -1;
    unsigned m = __match_any_sync(0xffffffffu, key);
    int leader = __ffs(m) - 1;
    if ((int)(threadIdx.x & 31) == leader && key >= 0)
        atomicAdd(&d_cnt[key], __popc(m));
}

// ---------------- single-block exclusive scan of degrees -> CSR starts, cursors, invdeg ----------------
__global__ void k_scan(int n) {
    __shared__ int sm[1024];
    int t = threadIdx.x;
    int CH = (n + 1023) >> 10;
    int base = t * CH, end = min(base + CH, n);
    int s = 0;
    for (int i = base; i < end; ++i) s += d_deg[i];
    sm[t] = s;
    __syncthreads();
    for (int off = 1; off < 1024; off <<= 1) {
        int v = sm[t];
        if (t >= off) v += sm[t - off];
        __syncthreads();
        sm[t] = v;
        __syncthreads();
    }
    int run = (t > 0) ? sm[t - 1] : 0;
    for (int i = base; i < end; ++i) {
        int dg = d_deg[i];
        d_start[i] = run;
        d_cur[i] = run;
        d_invdeg[i] = 1.0f / fmaxf((float)dg, 1.0f);
        run += dg;
    }
}

// ---------------- fill adjacency (src grouped by dst) ----------------
__global__ void k_fill(const int* __restrict__ ei, int e) {
    int i = blockIdx.x * blockDim.x + threadIdx.x;
    if (i >= e) return;
    int s = ei[i];
    int d = ei[e + i];
    int p = atomicAdd(&d_cur[d], 1);
    d_adj[p] = s;
}

// ---------------- gather: warp per node, atomic-free neighbor sum ----------------
__global__ void k_gather(const float* __restrict__ x, int n) {
    int gw = (blockIdx.x * blockDim.x + threadIdx.x) >> 5;
    int lane = threadIdx.x & 31;
    if (gw >= n) return;
    int s0 = d_start[gw];
    int dg = d_deg[gw];
    const float4* x4 = (const float4*)x;
    float4 a = make_float4(0.f, 0.f, 0.f, 0.f);
#pragma unroll 4
    for (int j = 0; j < dg; ++j) {
        int s = __ldg(&d_adj[s0 + j]);
        float4 v = x4[(size_t)s * 32 + lane];
        a.x += v.x; a.y += v.y; a.z += v.z; a.w += v.w;
    }
    ((float4*)d_agg)[(size_t)gw * 32 + lane] = a;
}

// ---------------- barrier-free tensor GEMM + GELU + stats ----------------
// 2-term fp16 split: A = ah + al (exact to ~2^-22), B single fp16.
#define MMA_F16(c, a, b0v, b1v)                                            \
    asm volatile(                                                          \
        "mma.sync.aligned.m16n8k16.row.col.f32.f16.f16.f32 "               \
        "{%0,%1,%2,%3},{%4,%5,%6,%7},{%8,%9},{%0,%1,%2,%3};\n"             \
        : "+f"(c[0]), "+f"(c[1]), "+f"(c[2]), "+f"(c[3])                   \
        : "r"(a[0]), "r"(a[1]), "r"(a[2]), "r"(a[3]), "r"(b0v), "r"(b1v))

__device__ __forceinline__ void splith(float2 v, unsigned& h, unsigned& l) {
    __half2 hv = __float22half2_rn(v);
    float2 hf = __half22float2(hv);
    __half2 lv = __float22half2_rn(make_float2(v.x - hf.x, v.y - hf.y));
    h = *reinterpret_cast<unsigned*>(&hv);
    l = *reinterpret_cast<unsigned*>(&lv);
}

__global__ __launch_bounds__(256, 3) void k_gemm(
    const float* __restrict__ x, const float* __restrict__ bl,
    const int* __restrict__ batch, int n)
{
    __shared__ float red_s[8][66];
    __shared__ float red_q[8][66];
    __shared__ int   bsm[64];
    __shared__ float bias_s[128];

    int t = threadIdx.x, wid = t >> 5, lane = t & 31;
    int r = lane >> 2, q4 = lane & 3;
    int wm = wid >> 1, wn = wid & 1;
    int n0 = blockIdx.x * 64;

    if (t < 64) bsm[t] = (n0 + t < n) ? batch[n0 + t] : -1;
    if (t < 128) bias_s[t] = bl[t];

    int row0 = n0 + wm * 16 + r;
    int row1 = row0 + 8;
    bool v0 = row0 < n, v1 = row1 < n;
    int rc0 = v0 ? row0 : 0, rc1 = v1 ? row1 : 0;
    float i0 = v0 ? d_invdeg[row0] : 0.f;
    float i1 = v1 ? d_invdeg[row1] : 0.f;
    float x0s = v0 ? 1.f : 0.f, x1s = v1 ? 1.f : 0.f;

    float acc[8][4];
#pragma unroll
    for (int nt = 0; nt < 8; ++nt)
#pragma unroll
        for (int j = 0; j < 4; ++j) acc[nt][j] = 0.f;

    // prefetch chunk 0 (agg operand)
    float2 b0, b1, b2, b3;
    {
        int kof = q4 * 2;
        b0 = *(const float2*)(d_agg + (size_t)rc0 * DD + kof);
        b1 = *(const float2*)(d_agg + (size_t)rc1 * DD + kof);
        b2 = *(const float2*)(d_agg + (size_t)rc0 * DD + kof + 8);
        b3 = *(const float2*)(d_agg + (size_t)rc1 * DD + kof + 8);
    }

#pragma unroll
    for (int cc = 0; cc < 16; ++cc) {
        float2 c0 = b0, c1 = b1, c2 = b2, c3 = b3;
        if (cc < 15) {
            const float* P = ((cc + 1) < 8) ? d_agg : x;
            int kof = ((cc + 1) & 7) * 16 + q4 * 2;
            b0 = *(const float2*)(P + (size_t)rc0 * DD + kof);
            b1 = *(const float2*)(P + (size_t)rc1 * DD + kof);
            b2 = *(const float2*)(P + (size_t)rc0 * DD + kof + 8);
            b3 = *(const float2*)(P + (size_t)rc1 * DD + kof + 8);
        }
        float s0 = (cc < 8) ? i0 : x0s;
        float s1 = (cc < 8) ? i1 : x1s;
        c0.x *= s0; c0.y *= s0; c2.x *= s0; c2.y *= s0;
        c1.x *= s1; c1.y *= s1; c3.x *= s1; c3.y *= s1;
        unsigned ah[4], al[4];
        splith(c0, ah[0], al[0]);
        splith(c1, ah[1], al[1]);
        splith(c2, ah[2], al[2]);
        splith(c3, ah[3], al[3]);
#pragma unroll
        for (int nt = 0; nt < 8; ++nt) {
            uint2 B = d_Wpk[(cc * 128 + wn * 64 + nt * 8 + r) * 4 + q4];
            MMA_F16(acc[nt], ah, B.x, B.y);
            MMA_F16(acc[nt], al, B.x, B.y);
        }
    }

    __syncthreads();  // bsm / bias_s visible

    // bias + exact GELU
#pragma unroll
    for (int nt = 0; nt < 8; ++nt) {
        int d0 = wn * 64 + nt * 8 + q4 * 2;
        float bb0 = bias_s[d0], bb1 = bias_s[d0 + 1];
        acc[nt][0] += bb0; acc[nt][1] += bb1;
        acc[nt][2] += bb0; acc[nt][3] += bb1;
#pragma unroll
        for (int j = 0; j < 4; ++j) {
            float v = acc[nt][j];
            acc[nt][j] = 0.5f * v * (1.0f + erff(v * 0.70710678118654752f));
        }
    }

    // write f
#pragma unroll
    for (int nt = 0; nt < 8; ++nt) {
        int col = wn * 64 + nt * 8 + q4 * 2;
        if (v0) *(float2*)(d_f + (size_t)row0 * DD + col) = make_float2(acc[nt][0], acc[nt][1]);
        if (v1) *(float2*)(d_f + (size_t)row1 * DD + col) = make_float2(acc[nt][2], acc[nt][3]);
    }

    // per-graph sum / sumsq
    int last = min(63, n - 1 - n0);
    int glo = bsm[0], ghi = bsm[last];
    int g0r = bsm[wm * 16 + r];
    int g1r = bsm[wm * 16 + r + 8];
    for (int g = glo; g <= ghi; ++g) {
        float s[16], q[16];
#pragma unroll
        for (int i = 0; i < 16; ++i) { s[i] = 0.f; q[i] = 0.f; }
        if (g0r == g)
#pragma unroll
            for (int nt = 0; nt < 8; ++nt) {
                float a0 = acc[nt][0], a1 = acc[nt][1];
                s[nt * 2] += a0; s[nt * 2 + 1] += a1;
                q[nt * 2] += a0 * a0; q[nt * 2 + 1] += a1 * a1;
            }
        if (g1r == g)
#pragma unroll
            for (int nt = 0; nt < 8; ++nt) {
                float a2 = acc[nt][2], a3 = acc[nt][3];
                s[nt * 2] += a2; s[nt * 2 + 1] += a3;
                q[nt * 2] += a2 * a2; q[nt * 2 + 1] += a3 * a3;
            }
#pragma unroll
        for (int off = 4; off < 32; off <<= 1)
#pragma unroll
            for (int i = 0; i < 16; ++i) {
                s[i] += __shfl_xor_sync(0xffffffffu, s[i], off);
                q[i] += __shfl_xor_sync(0xffffffffu, q[i], off);
            }
        if (lane < 4)
#pragma unroll
            for (int nt = 0; nt < 8; ++nt) {
                red_s[wid][nt * 8 + lane * 2]     = s[nt * 2];
                red_s[wid][nt * 8 + lane * 2 + 1] = s[nt * 2 + 1];
                red_q[wid][nt * 8 + lane * 2]     = q[nt * 2];
                red_q[wid][nt * 8 + lane * 2 + 1] = q[nt * 2 + 1];
            }
        __syncthreads();
        if (t < 128) {
            int wn_ = t >> 6, dl = t & 63;
            float ts = 0.f, tq = 0.f;
#pragma unroll
            for (int wm_ = 0; wm_ < 4; ++wm_) {
                ts += red_s[wm_ * 2 + wn_][dl];
                tq += red_q[wm_ * 2 + wn_][dl];
            }
            atomicAdd(&d_gsum[g * DD + t], ts);
            atomicAdd(&d_gsumsq[g * DD + t], tq);
        }
        __syncthreads();
    }
}

// ---------------- per-(graph,dim) norm params ----------------
__global__ void k_params(const float* __restrict__ gw, const float* __restrict__ gb,
                         const float* __restrict__ ms) {
    int i = blockIdx.x * blockDim.x + threadIdx.x;
    if (i >= GG * DD) return;
    int g = i >> 7, d = i & 127;
    float c = fmaxf((float)d_cnt[g], 1.f);
    float mean = d_gsum[i] / c;
    float m2 = d_gsumsq[i] / c;
    float m = ms[d];
    float var = m2 - m * (2.f - m) * mean * mean;
    var = fmaxf(var, 0.f);
    float rstd = rsqrtf(var + 1e-5f);
    float A = gw[d] * rstd;
    d_An[i] = A;
    d_Bn[i] = gb[d] - m * mean * A;
}

// ---------------- final: normalize + residual ----------------
__global__ void k_final(const float* __restrict__ x, const int* __restrict__ batch,
                        float* __restrict__ out, int n) {
    int i = blockIdx.x * blockDim.x + threadIdx.x;
    if (i >= n * 32) return;
    int node = i >> 5, c = i & 31;
    int g = batch[node];
    float4 f = ((const float4*)d_f)[i];
    float4 xv = ((const float4*)x)[i];
    float4 a = ((const float4*)d_An)[g * 32 + c];
    float4 b = ((const float4*)d_Bn)[g * 32 + c];
    float4 o;
    o.x = f.x * a.x + b.x + xv.x;
    o.y = f.y * a.y + b.y + xv.y;
    o.z = f.z * a.z + b.z + xv.z;
    o.w = f.w * a.w + b.w + xv.w;
    ((float4*)out)[i] = o;
}

// ---------------- launch ----------------
extern "C" void kernel_launch(void* const* d_in, const int* in_sizes, int n_in,
                              void* d_out, int out_size) {
    const float* x     = (const float*)d_in[0];
    const int*   ei    = (const int*)d_in[1];
    const int*   batch = (const int*)d_in[2];
    const float* Wl  = (const float*)d_in[4];
    const float* bl  = (const float*)d_in[5];
    const float* Wr  = (const float*)d_in[6];
    const float* gw  = (const float*)d_in[7];
    const float* gb  = (const float*)d_in[8];
    const float* msc = (const float*)d_in[9];
    float* out = (float*)d_out;

    int n = in_sizes[0] / DD;
    int e = in_sizes[1] / 2;

    k_prep<<<(n + 255) / 256, 256>>>(Wl, Wr, n);
    k_hist<<<(e + 255) / 256, 256>>>(ei, batch, e, n);
    k_scan<<<1, 1024>>>(n);
    k_fill<<<(e + 255) / 256, 256>>>(ei, e);
    k_gather<<<(n * 32 + 255) / 256, 256>>>(x, n);
    k_gemm<<<(n + 63) / 64, 256>>>(x, bl, batch, n);
    k_params<<<4, 256>>>(gw, gb, msc);
    k_final<<<(n * 32 + 255) / 256, 256>>>(x, batch, out, n);
}

// round 7
// speedup vs baseline: 1.4479x; 1.4479x over previous
#include <cuda_runtime.h>
#include <cuda_fp16.h>
#include <math.h>

#define NN 50000
#define EE 600000
#define DD 128
#define GG 8

// ---------------- scratch (device globals: no allocation allowed) ----------------
__device__ float d_agg[NN * DD];
__device__ float d_f[NN * DD];
__device__ int   d_deg[NN];
__device__ int   d_start[NN];
__device__ int   d_cur[NN];
__device__ int   d_adj[EE];
__device__ float d_invdeg[NN];
__device__ float d_gsum[GG * DD];
__device__ float d_gsumsq[GG * DD];
__device__ int   d_cnt[GG];
__device__ float d_An[GG * DD];
__device__ float d_Bn[GG * DD];
__device__ int   d_bsum[256];
__device__ int   d_boff[256];
__device__ uint2 d_Wpk[8192];   // fp16 packed W fragments: [(op*8+c)*128 + d]*4 + q4

// ---------------- prep: zero scratch + pack weights to fp16 fragment layout ----------------
__global__ void k_prep(const float* __restrict__ Wl, const float* __restrict__ Wr, int n) {
    int i = blockIdx.x * blockDim.x + threadIdx.x;
    if (i < n) d_deg[i] = 0;
    if (i < GG * DD) { d_gsum[i] = 0.f; d_gsumsq[i] = 0.f; }
    if (i < GG) d_cnt[i] = 0;
    if (i < 8192) {
        int q4 = i & 3, d = (i >> 2) & 127, c = (i >> 9) & 7, op = i >> 12;
        const float* W = op ? Wr : Wl;
        int k0 = c * 16;
        float2 p0 = *(const float2*)(W + (size_t)d * DD + k0 + q4 * 2);
        float2 p1 = *(const float2*)(W + (size_t)d * DD + k0 + 8 + q4 * 2);
        __half2 h0 = __float22half2_rn(p0);
        __half2 h1 = __float22half2_rn(p1);
        uint2 o;
        o.x = *reinterpret_cast<unsigned*>(&h0);
        o.y = *reinterpret_cast<unsigned*>(&h1);
        d_Wpk[i] = o;
    }
}

// ---------------- histogram of dst degrees + per-graph node counts ----------------
__global__ void k_hist(const int* __restrict__ ei, const int* __restrict__ batch, int e, int n) {
    int i = blockIdx.x * blockDim.x + threadIdx.x;
    if (i < e) atomicAdd(&d_deg[ei[e + i]], 1);
    int key = (i < n) ? batch[i] : -1;
    unsigned m = __match_any_sync(0xffffffffu, key);
    int leader = __ffs(m) - 1;
    if ((int)(threadIdx.x & 31) == leader && key >= 0)
        atomicAdd(&d_cnt[key], __popc(m));
}

// ---------------- hierarchical scan: block sums -> scan sums -> per-block rescan ----------------
__global__ void k_scan1(int n) {
    __shared__ int sm[256];
    int t = threadIdx.x, i = blockIdx.x * 256 + t;
    sm[t] = (i < n) ? d_deg[i] : 0;
    __syncthreads();
#pragma unroll
    for (int off = 128; off; off >>= 1) {
        if (t < off) sm[t] += sm[t + off];
        __syncthreads();
    }
    if (t == 0) d_bsum[blockIdx.x] = sm[0];
}

__global__ void k_scan2(int nb) {
    __shared__ int sm[256];
    int t = threadIdx.x;
    int own = (t < nb) ? d_bsum[t] : 0;
    sm[t] = own;
    __syncthreads();
#pragma unroll
    for (int off = 1; off < 256; off <<= 1) {
        int v = sm[t];
        int a = (t >= off) ? sm[t - off] : 0;
        __syncthreads();
        sm[t] = v + a;
        __syncthreads();
    }
    if (t < nb) d_boff[t] = sm[t] - own;   // exclusive
}

__global__ void k_scan3(int n) {
    __shared__ int sm[256];
    int t = threadIdx.x, i = blockIdx.x * 256 + t;
    int v = (i < n) ? d_deg[i] : 0;
    sm[t] = v;
    __syncthreads();
#pragma unroll
    for (int off = 1; off < 256; off <<= 1) {
        int a = sm[t];
        int b = (t >= off) ? sm[t - off] : 0;
        __syncthreads();
        sm[t] = a + b;
        __syncthreads();
    }
    if (i < n) {
        int excl = sm[t] - v + d_boff[blockIdx.x];
        d_start[i] = excl;
        d_cur[i] = excl;
        d_invdeg[i] = 1.0f / fmaxf((float)v, 1.0f);
    }
}

// ---------------- fill adjacency (2 edges per thread for ILP) ----------------
__global__ void k_fill(const int* __restrict__ ei, int e) {
    int i0 = (blockIdx.x * blockDim.x + threadIdx.x) * 2;
#pragma unroll
    for (int u = 0; u < 2; ++u) {
        int i = i0 + u;
        if (i < e) {
            int s = ei[i];
            int d = ei[e + i];
            int p = atomicAdd(&d_cur[d], 1);
            d_adj[p] = s;
        }
    }
}

// ---------------- gather: warp per node, atomic-free neighbor sum ----------------
__global__ void k_gather(const float* __restrict__ x, int n) {
    int gw = (blockIdx.x * blockDim.x + threadIdx.x) >> 5;
    int lane = threadIdx.x & 31;
    if (gw >= n) return;
    int s0 = d_start[gw];
    int dg = d_deg[gw];
    const float4* x4 = (const float4*)x;
    float4 a = make_float4(0.f, 0.f, 0.f, 0.f);
#pragma unroll 4
    for (int j = 0; j < dg; ++j) {
        int s = __ldg(&d_adj[s0 + j]);
        float4 v = x4[(size_t)s * 32 + lane];
        a.x += v.x; a.y += v.y; a.z += v.z; a.w += v.w;
    }
    ((float4*)d_agg)[(size_t)gw * 32 + lane] = a;
}

// ---------------- barrier-free tensor GEMM + GELU + stats ----------------
#define MMA_F16(c, a, b0v, b1v)                                            \
    asm volatile(                                                          \
        "mma.sync.aligned.m16n8k16.row.col.f32.f16.f16.f32 "               \
        "{%0,%1,%2,%3},{%4,%5,%6,%7},{%8,%9},{%0,%1,%2,%3};\n"             \
        : "+f"(c[0]), "+f"(c[1]), "+f"(c[2]), "+f"(c[3])                   \
        : "r"(a[0]), "r"(a[1]), "r"(a[2]), "r"(a[3]), "r"(b0v), "r"(b1v))

__device__ __forceinline__ void splith(float2 v, unsigned& h, unsigned& l) {
    __half2 hv = __float22half2_rn(v);
    float2 hf = __half22float2(hv);
    __half2 lv = __float22half2_rn(make_float2(v.x - hf.x, v.y - hf.y));
    h = *reinterpret_cast<unsigned*>(&hv);
    l = *reinterpret_cast<unsigned*>(&lv);
}

__global__ __launch_bounds__(256, 2) void k_gemm(
    const float* __restrict__ x, const float* __restrict__ bl,
    const int* __restrict__ batch, int n)
{
    __shared__ float red_s[8][66];
    __shared__ float red_q[8][66];
    __shared__ int   bsm[64];
    __shared__ float bias_s[128];

    int t = threadIdx.x, wid = t >> 5, lane = t & 31;
    int r = lane >> 2, q4 = lane & 3;
    int wm = wid >> 1, wn = wid & 1;
    int n0 = blockIdx.x * 64;

    if (t < 64) bsm[t] = (n0 + t < n) ? batch[n0 + t] : -1;
    if (t < 128) bias_s[t] = bl[t];

    int row0 = n0 + wm * 16 + r;
    int row1 = row0 + 8;
    bool v0 = row0 < n, v1 = row1 < n;
    int rc0 = v0 ? row0 : 0, rc1 = v1 ? row1 : 0;
    float i0 = v0 ? d_invdeg[row0] : 0.f;
    float i1 = v1 ? d_invdeg[row1] : 0.f;
    float x0s = v0 ? 1.f : 0.f, x1s = v1 ? 1.f : 0.f;

    float acc[8][4];
#pragma unroll
    for (int nt = 0; nt < 8; ++nt)
#pragma unroll
        for (int j = 0; j < 4; ++j) acc[nt][j] = 0.f;

    // prefetch chunk 0 (agg operand)
    float2 b0, b1, b2, b3;
    {
        int kof = q4 * 2;
        b0 = *(const float2*)(d_agg + (size_t)rc0 * DD + kof);
        b1 = *(const float2*)(d_agg + (size_t)rc1 * DD + kof);
        b2 = *(const float2*)(d_agg + (size_t)rc0 * DD + kof + 8);
        b3 = *(const float2*)(d_agg + (size_t)rc1 * DD + kof + 8);
    }

#pragma unroll
    for (int cc = 0; cc < 16; ++cc) {
        float2 c0 = b0, c1 = b1, c2 = b2, c3 = b3;
        if (cc < 15) {
            const float* P = ((cc + 1) < 8) ? d_agg : x;
            int kof = ((cc + 1) & 7) * 16 + q4 * 2;
            b0 = *(const float2*)(P + (size_t)rc0 * DD + kof);
            b1 = *(const float2*)(P + (size_t)rc1 * DD + kof);
            b2 = *(const float2*)(P + (size_t)rc0 * DD + kof + 8);
            b3 = *(const float2*)(P + (size_t)rc1 * DD + kof + 8);
        }
        float s0 = (cc < 8) ? i0 : x0s;
        float s1 = (cc < 8) ? i1 : x1s;
        c0.x *= s0; c0.y *= s0; c2.x *= s0; c2.y *= s0;
        c1.x *= s1; c1.y *= s1; c3.x *= s1; c3.y *= s1;
        unsigned ah[4], al[4];
        splith(c0, ah[0], al[0]);
        splith(c1, ah[1], al[1]);
        splith(c2, ah[2], al[2]);
        splith(c3, ah[3], al[3]);
#pragma unroll
        for (int nt = 0; nt < 8; ++nt) {
            uint2 B = d_Wpk[(cc * 128 + wn * 64 + nt * 8 + r) * 4 + q4];
            MMA_F16(acc[nt], ah, B.x, B.y);
            MMA_F16(acc[nt], al, B.x, B.y);
        }
    }

    __syncthreads();  // bsm / bias_s visible

    // bias + exact GELU
#pragma unroll
    for (int nt = 0; nt < 8; ++nt) {
        int d0 = wn * 64 + nt * 8 + q4 * 2;
        float bb0 = bias_s[d0], bb1 = bias_s[d0 + 1];
        acc[nt][0] += bb0; acc[nt][1] += bb1;
        acc[nt][2] += bb0; acc[nt][3] += bb1;
#pragma unroll
        for (int j = 0; j < 4; ++j) {
            float v = acc[nt][j];
            acc[nt][j] = 0.5f * v * (1.0f + erff(v * 0.70710678118654752f));
        }
    }

    // write f
#pragma unroll
    for (int nt = 0; nt < 8; ++nt) {
        int col = wn * 64 + nt * 8 + q4 * 2;
        if (v0) *(float2*)(d_f + (size_t)row0 * DD + col) = make_float2(acc[nt][0], acc[nt][1]);
        if (v1) *(float2*)(d_f + (size_t)row1 * DD + col) = make_float2(acc[nt][2], acc[nt][3]);
    }

    // per-graph sum / sumsq
    int last = min(63, n - 1 - n0);
    int glo = bsm[0], ghi = bsm[last];
    int g0r = bsm[wm * 16 + r];
    int g1r = bsm[wm * 16 + r + 8];
    for (int g = glo; g <= ghi; ++g) {
        float s[16], q[16];
#pragma unroll
        for (int i = 0; i < 16; ++i) { s[i] = 0.f; q[i] = 0.f; }
        if (g0r == g)
#pragma unroll
            for (int nt = 0; nt < 8; ++nt) {
                float a0 = acc[nt][0], a1 = acc[nt][1];
                s[nt * 2] += a0; s[nt * 2 + 1] += a1;
                q[nt * 2] += a0 * a0; q[nt * 2 + 1] += a1 * a1;
            }
        if (g1r == g)
#pragma unroll
            for (int nt = 0; nt < 8; ++nt) {
                float a2 = acc[nt][2], a3 = acc[nt][3];
                s[nt * 2] += a2; s[nt * 2 + 1] += a3;
                q[nt * 2] += a2 * a2; q[nt * 2 + 1] += a3 * a3;
            }
#pragma unroll
        for (int off = 4; off < 32; off <<= 1)
#pragma unroll
            for (int i = 0; i < 16; ++i) {
                s[i] += __shfl_xor_sync(0xffffffffu, s[i], off);
                q[i] += __shfl_xor_sync(0xffffffffu, q[i], off);
            }
        if (lane < 4)
#pragma unroll
            for (int nt = 0; nt < 8; ++nt) {
                red_s[wid][nt * 8 + lane * 2]     = s[nt * 2];
                red_s[wid][nt * 8 + lane * 2 + 1] = s[nt * 2 + 1];
                red_q[wid][nt * 8 + lane * 2]     = q[nt * 2];
                red_q[wid][nt * 8 + lane * 2 + 1] = q[nt * 2 + 1];
            }
        __syncthreads();
        if (t < 128) {
            int wn_ = t >> 6, dl = t & 63;
            float ts = 0.f, tq = 0.f;
#pragma unroll
            for (int wm_ = 0; wm_ < 4; ++wm_) {
                ts += red_s[wm_ * 2 + wn_][dl];
                tq += red_q[wm_ * 2 + wn_][dl];
            }
            atomicAdd(&d_gsum[g * DD + t], ts);
            atomicAdd(&d_gsumsq[g * DD + t], tq);
        }
        __syncthreads();
    }
}

// ---------------- per-(graph,dim) norm params ----------------
__global__ void k_params(const float* __restrict__ gw, const float* __restrict__ gb,
                         const float* __restrict__ ms) {
    int i = blockIdx.x * blockDim.x + threadIdx.x;
    if (i >= GG * DD) return;
    int g = i >> 7, d = i & 127;
    float c = fmaxf((float)d_cnt[g], 1.f);
    float mean = d_gsum[i] / c;
    float m2 = d_gsumsq[i] / c;
    float m = ms[d];
    float var = m2 - m * (2.f - m) * mean * mean;
    var = fmaxf(var, 0.f);
    float rstd = rsqrtf(var + 1e-5f);
    float A = gw[d] * rstd;
    d_An[i] = A;
    d_Bn[i] = gb[d] - m * mean * A;
}

// ---------------- final: normalize + residual ----------------
__global__ void k_final(const float* __restrict__ x, const int* __restrict__ batch,
                        float* __restrict__ out, int n) {
    int i = blockIdx.x * blockDim.x + threadIdx.x;
    if (i >= n * 32) return;
    int node = i >> 5, c = i & 31;
    int g = batch[node];
    float4 f = ((const float4*)d_f)[i];
    float4 xv = ((const float4*)x)[i];
    float4 a = ((const float4*)d_An)[g * 32 + c];
    float4 b = ((const float4*)d_Bn)[g * 32 + c];
    float4 o;
    o.x = f.x * a.x + b.x + xv.x;
    o.y = f.y * a.y + b.y + xv.y;
    o.z = f.z * a.z + b.z + xv.z;
    o.w = f.w * a.w + b.w + xv.w;
    ((float4*)out)[i] = o;
}

// ---------------- launch ----------------
extern "C" void kernel_launch(void* const* d_in, const int* in_sizes, int n_in,
                              void* d_out, int out_size) {
    const float* x     = (const float*)d_in[0];
    const int*   ei    = (const int*)d_in[1];
    const int*   batch = (const int*)d_in[2];
    const float* Wl  = (const float*)d_in[4];
    const float* bl  = (const float*)d_in[5];
    const float* Wr  = (const float*)d_in[6];
    const float* gw  = (const float*)d_in[7];
    const float* gb  = (const float*)d_in[8];
    const float* msc = (const float*)d_in[9];
    float* out = (float*)d_out;

    int n = in_sizes[0] / DD;
    int e = in_sizes[1] / 2;
    int nb = (n + 255) / 256;

    k_prep<<<(n + 255) / 256, 256>>>(Wl, Wr, n);
    k_hist<<<(e + 255) / 256, 256>>>(ei, batch, e, n);
    k_scan1<<<nb, 256>>>(n);
    k_scan2<<<1, 256>>>(nb);
    k_scan3<<<nb, 256>>>(n);
    k_fill<<<(e / 2 + 255) / 256, 256>>>(ei, e);
    k_gather<<<(n * 32 + 255) / 256, 256>>>(x, n);
    k_gemm<<<(n + 63) / 64, 256>>>(x, bl, batch, n);
    k_params<<<4, 256>>>(gw, gb, msc);
    k_final<<<(n * 32 + 255) / 256, 256>>>(x, batch, out, n);
}

// round 8
// speedup vs baseline: 1.7849x; 1.2327x over previous
#include <cuda_runtime.h>
#include <cuda_fp16.h>
#include <math.h>

#define NN 50000
#define EE 600000
#define DD 128
#define GG 8

// ---------------- scratch (device globals: no allocation allowed) ----------------
__device__ float d_f[NN * DD];
__device__ int   d_deg[NN];
__device__ int   d_start[NN];
__device__ int   d_cur[NN];
__device__ int   d_adj[EE];
__device__ float d_invdeg[NN];
__device__ float d_gsum[GG * DD];
__device__ float d_gsumsq[GG * DD];
__device__ int   d_cnt[GG];
__device__ float d_An[GG * DD];
__device__ float d_Bn[GG * DD];
__device__ int   d_bsum[256];
__device__ int   d_boff[256];
__device__ uint2 d_Wpk[8192];   // fp16 packed W fragments: [(op*8+c)*128 + d]*4 + q4

// ---------------- prep: zero scratch + pack weights to fp16 fragment layout ----------------
__global__ void k_prep(const float* __restrict__ Wl, const float* __restrict__ Wr, int n) {
    int i = blockIdx.x * blockDim.x + threadIdx.x;
    if (i < n) d_deg[i] = 0;
    if (i < GG * DD) { d_gsum[i] = 0.f; d_gsumsq[i] = 0.f; }
    if (i < GG) d_cnt[i] = 0;
    if (i < 8192) {
        int q4 = i & 3, d = (i >> 2) & 127, c = (i >> 9) & 7, op = i >> 12;
        const float* W = op ? Wr : Wl;
        int k0 = c * 16;
        float2 p0 = *(const float2*)(W + (size_t)d * DD + k0 + q4 * 2);
        float2 p1 = *(const float2*)(W + (size_t)d * DD + k0 + 8 + q4 * 2);
        __half2 h0 = __float22half2_rn(p0);
        __half2 h1 = __float22half2_rn(p1);
        uint2 o;
        o.x = *reinterpret_cast<unsigned*>(&h0);
        o.y = *reinterpret_cast<unsigned*>(&h1);
        d_Wpk[i] = o;
    }
}

// ---------------- histogram of dst degrees + per-graph node counts ----------------
__global__ void k_hist(const int* __restrict__ ei, const int* __restrict__ batch, int e, int n) {
    int i = blockIdx.x * blockDim.x + threadIdx.x;
    if (i < e) atomicAdd(&d_deg[ei[e + i]], 1);
    int key = (i < n) ? batch[i] : -1;
    unsigned m = __match_any_sync(0xffffffffu, key);
    int leader = __ffs(m) - 1;
    if ((int)(threadIdx.x & 31) == leader && key >= 0)
        atomicAdd(&d_cnt[key], __popc(m));
}

// ---------------- hierarchical scan (shuffle-based) ----------------
__global__ void k_scan1(int n) {
    __shared__ int sm[8];
    int t = threadIdx.x, i = blockIdx.x * 256 + t;
    int lane = t & 31, w = t >> 5;
    int v = (i < n) ? d_deg[i] : 0;
#pragma unroll
    for (int off = 16; off; off >>= 1) v += __shfl_xor_sync(0xffffffffu, v, off);
    if (lane == 0) sm[w] = v;
    __syncthreads();
    if (t == 0) {
        int s = 0;
#pragma unroll
        for (int k = 0; k < 8; ++k) s += sm[k];
        d_bsum[blockIdx.x] = s;
    }
}

__global__ void k_scan2(int nb) {
    __shared__ int ws[8];
    int t = threadIdx.x, lane = t & 31, w = t >> 5;
    int own = (t < nb) ? d_bsum[t] : 0;
    int v = own;
#pragma unroll
    for (int off = 1; off < 32; off <<= 1) {
        int u = __shfl_up_sync(0xffffffffu, v, off);
        if (lane >= off) v += u;
    }
    if (lane == 31) ws[w] = v;
    __syncthreads();
    if (w == 0) {
        int sv = (lane < 8) ? ws[lane] : 0;
#pragma unroll
        for (int off = 1; off < 8; off <<= 1) {
            int u = __shfl_up_sync(0xffffffffu, sv, off);
            if (lane >= off) sv += u;
        }
        if (lane < 8) ws[lane] = sv;
    }
    __syncthreads();
    int add = (w > 0) ? ws[w - 1] : 0;
    if (t < nb) d_boff[t] = v + add - own;   // exclusive
}

__global__ void k_scan3(int n) {
    __shared__ int ws[8];
    int t = threadIdx.x, i = blockIdx.x * 256 + t;
    int lane = t & 31, w = t >> 5;
    int own = (i < n) ? d_deg[i] : 0;
    int v = own;
#pragma unroll
    for (int off = 1; off < 32; off <<= 1) {
        int u = __shfl_up_sync(0xffffffffu, v, off);
        if (lane >= off) v += u;
    }
    if (lane == 31) ws[w] = v;
    __syncthreads();
    if (w == 0) {
        int sv = (lane < 8) ? ws[lane] : 0;
#pragma unroll
        for (int off = 1; off < 8; off <<= 1) {
            int u = __shfl_up_sync(0xffffffffu, sv, off);
            if (lane >= off) sv += u;
        }
        if (lane < 8) ws[lane] = sv;
    }
    __syncthreads();
    int add = (w > 0) ? ws[w - 1] : 0;
    if (i < n) {
        int excl = v + add - own + d_boff[blockIdx.x];
        d_start[i] = excl;
        d_cur[i] = excl;
        d_invdeg[i] = 1.0f / fmaxf((float)own, 1.0f);
    }
}

// ---------------- fill adjacency (4 edges per thread for ILP) ----------------
__global__ void k_fill(const int* __restrict__ ei, int e) {
    int i0 = (blockIdx.x * blockDim.x + threadIdx.x) * 4;
#pragma unroll
    for (int u = 0; u < 4; ++u) {
        int i = i0 + u;
        if (i < e) {
            int s = ei[i];
            int d = ei[e + i];
            int p = atomicAdd(&d_cur[d], 1);
            d_adj[p] = s;
        }
    }
}

// ---------------- fused gather + tensor GEMM + GELU + stats ----------------
#define MMA_F16(c, a, b0v, b1v)                                            \
    asm volatile(                                                          \
        "mma.sync.aligned.m16n8k16.row.col.f32.f16.f16.f32 "               \
        "{%0,%1,%2,%3},{%4,%5,%6,%7},{%8,%9},{%0,%1,%2,%3};\n"             \
        : "+f"(c[0]), "+f"(c[1]), "+f"(c[2]), "+f"(c[3])                   \
        : "r"(a[0]), "r"(a[1]), "r"(a[2]), "r"(a[3]), "r"(b0v), "r"(b1v))

__device__ __forceinline__ void splith(float2 v, unsigned& h, unsigned& l) {
    __half2 hv = __float22half2_rn(v);
    float2 hf = __half22float2(hv);
    __half2 lv = __float22half2_rn(make_float2(v.x - hf.x, v.y - hf.y));
    h = *reinterpret_cast<unsigned*>(&hv);
    l = *reinterpret_cast<unsigned*>(&lv);
}

#define ASTR 132

__global__ __launch_bounds__(256, 2) void k_gemm(
    const float* __restrict__ x, const float* __restrict__ bl,
    const int* __restrict__ batch, int n)
{
    __shared__ float agg_s[64 * ASTR];
    __shared__ float red_s[8][66];
    __shared__ float red_q[8][66];
    __shared__ int   bsm[64];
    __shared__ float bias_s[128];

    int t = threadIdx.x, wid = t >> 5, lane = t & 31;
    int r = lane >> 2, q4 = lane & 3;
    int wm = wid >> 1, wn = wid & 1;
    int n0 = blockIdx.x * 64;

    if (t < 64) bsm[t] = (n0 + t < n) ? batch[n0 + t] : -1;
    if (t < 128) bias_s[t] = bl[t];

    const float4* x4 = (const float4*)x;

    // ---- gather phase: warp wid gathers nodes wid*8 .. wid*8+7 into smem (scaled) ----
#pragma unroll 1
    for (int u = 0; u < 8; ++u) {
        int ln = wid * 8 + u;
        int gn = n0 + ln;
        float4 a = make_float4(0.f, 0.f, 0.f, 0.f);
        float inv = 0.f;
        if (gn < n) {
            int s0 = d_start[gn];
            int dg = d_deg[gn];
            inv = d_invdeg[gn];
#pragma unroll 4
            for (int j = 0; j < dg; ++j) {
                int s = __ldg(&d_adj[s0 + j]);
                float4 v = x4[(size_t)s * 32 + lane];
                a.x += v.x; a.y += v.y; a.z += v.z; a.w += v.w;
            }
        }
        a.x *= inv; a.y *= inv; a.z *= inv; a.w *= inv;
        *(float4*)&agg_s[ln * ASTR + lane * 4] = a;
    }
    __syncthreads();

    int row0 = n0 + wm * 16 + r;
    int row1 = row0 + 8;
    bool v0 = row0 < n, v1 = row1 < n;
    int rc0 = v0 ? row0 : 0, rc1 = v1 ? row1 : 0;
    float x0s = v0 ? 1.f : 0.f, x1s = v1 ? 1.f : 0.f;

    float acc[8][4];
#pragma unroll
    for (int nt = 0; nt < 8; ++nt)
#pragma unroll
        for (int j = 0; j < 4; ++j) acc[nt][j] = 0.f;

    // ---- chunks 0..7: A from smem (agg, pre-scaled) ----
    int ar0 = (wm * 16 + r) * ASTR;
    int ar1 = (wm * 16 + r + 8) * ASTR;
#pragma unroll
    for (int cc = 0; cc < 8; ++cc) {
        int kof = cc * 16 + q4 * 2;
        float2 c0 = *(const float2*)&agg_s[ar0 + kof];
        float2 c1 = *(const float2*)&agg_s[ar1 + kof];
        float2 c2 = *(const float2*)&agg_s[ar0 + kof + 8];
        float2 c3 = *(const float2*)&agg_s[ar1 + kof + 8];
        unsigned ah[4], al[4];
        splith(c0, ah[0], al[0]);
        splith(c1, ah[1], al[1]);
        splith(c2, ah[2], al[2]);
        splith(c3, ah[3], al[3]);
#pragma unroll
        for (int nt = 0; nt < 8; ++nt) {
            uint2 B = d_Wpk[(cc * 128 + wn * 64 + nt * 8 + r) * 4 + q4];
            MMA_F16(acc[nt], ah, B.x, B.y);
            MMA_F16(acc[nt], al, B.x, B.y);
        }
    }

    // ---- chunks 8..15: A from global x, prefetch chain ----
    float2 b0, b1, b2, b3;
    {
        int kof = q4 * 2;
        b0 = *(const float2*)(x + (size_t)rc0 * DD + kof);
        b1 = *(const float2*)(x + (size_t)rc1 * DD + kof);
        b2 = *(const float2*)(x + (size_t)rc0 * DD + kof + 8);
        b3 = *(const float2*)(x + (size_t)rc1 * DD + kof + 8);
    }
#pragma unroll
    for (int cc = 8; cc < 16; ++cc) {
        float2 c0 = b0, c1 = b1, c2 = b2, c3 = b3;
        if (cc < 15) {
            int kof = (cc - 7) * 16 + q4 * 2;
            b0 = *(const float2*)(x + (size_t)rc0 * DD + kof);
            b1 = *(const float2*)(x + (size_t)rc1 * DD + kof);
            b2 = *(const float2*)(x + (size_t)rc0 * DD + kof + 8);
            b3 = *(const float2*)(x + (size_t)rc1 * DD + kof + 8);
        }
        c0.x *= x0s; c0.y *= x0s; c2.x *= x0s; c2.y *= x0s;
        c1.x *= x1s; c1.y *= x1s; c3.x *= x1s; c3.y *= x1s;
        unsigned ah[4], al[4];
        splith(c0, ah[0], al[0]);
        splith(c1, ah[1], al[1]);
        splith(c2, ah[2], al[2]);
        splith(c3, ah[3], al[3]);
#pragma unroll
        for (int nt = 0; nt < 8; ++nt) {
            uint2 B = d_Wpk[(cc * 128 + wn * 64 + nt * 8 + r) * 4 + q4];
            MMA_F16(acc[nt], ah, B.x, B.y);
            MMA_F16(acc[nt], al, B.x, B.y);
        }
    }

    // bias + exact GELU
#pragma unroll
    for (int nt = 0; nt < 8; ++nt) {
        int d0 = wn * 64 + nt * 8 + q4 * 2;
        float bb0 = bias_s[d0], bb1 = bias_s[d0 + 1];
        acc[nt][0] += bb0; acc[nt][1] += bb1;
        acc[nt][2] += bb0; acc[nt][3] += bb1;
#pragma unroll
        for (int j = 0; j < 4; ++j) {
            float v = acc[nt][j];
            acc[nt][j] = 0.5f * v * (1.0f + erff(v * 0.70710678118654752f));
        }
    }

    // write f
#pragma unroll
    for (int nt = 0; nt < 8; ++nt) {
        int col = wn * 64 + nt * 8 + q4 * 2;
        if (v0) *(float2*)(d_f + (size_t)row0 * DD + col) = make_float2(acc[nt][0], acc[nt][1]);
        if (v1) *(float2*)(d_f + (size_t)row1 * DD + col) = make_float2(acc[nt][2], acc[nt][3]);
    }

    // per-graph sum / sumsq
    int last = min(63, n - 1 - n0);
    int glo = bsm[0], ghi = bsm[last];
    int g0r = bsm[wm * 16 + r];
    int g1r = bsm[wm * 16 + r + 8];
    for (int g = glo; g <= ghi; ++g) {
        float s[16], q[16];
#pragma unroll
        for (int i = 0; i < 16; ++i) { s[i] = 0.f; q[i] = 0.f; }
        if (g0r == g)
#pragma unroll
            for (int nt = 0; nt < 8; ++nt) {
                float a0 = acc[nt][0], a1 = acc[nt][1];
                s[nt * 2] += a0; s[nt * 2 + 1] += a1;
                q[nt * 2] += a0 * a0; q[nt * 2 + 1] += a1 * a1;
            }
        if (g1r == g)
#pragma unroll
            for (int nt = 0; nt < 8; ++nt) {
                float a2 = acc[nt][2], a3 = acc[nt][3];
                s[nt * 2] += a2; s[nt * 2 + 1] += a3;
                q[nt * 2] += a2 * a2; q[nt * 2 + 1] += a3 * a3;
            }
#pragma unroll
        for (int off = 4; off < 32; off <<= 1)
#pragma unroll
            for (int i = 0; i < 16; ++i) {
                s[i] += __shfl_xor_sync(0xffffffffu, s[i], off);
                q[i] += __shfl_xor_sync(0xffffffffu, q[i], off);
            }
        if (lane < 4)
#pragma unroll
            for (int nt = 0; nt < 8; ++nt) {
                red_s[wid][nt * 8 + lane * 2]     = s[nt * 2];
                red_s[wid][nt * 8 + lane * 2 + 1] = s[nt * 2 + 1];
                red_q[wid][nt * 8 + lane * 2]     = q[nt * 2];
                red_q[wid][nt * 8 + lane * 2 + 1] = q[nt * 2 + 1];
            }
        __syncthreads();
        if (t < 128) {
            int wn_ = t >> 6, dl = t & 63;
            float ts = 0.f, tq = 0.f;
#pragma unroll
            for (int wm_ = 0; wm_ < 4; ++wm_) {
                ts += red_s[wm_ * 2 + wn_][dl];
                tq += red_q[wm_ * 2 + wn_][dl];
            }
            atomicAdd(&d_gsum[g * DD + t], ts);
            atomicAdd(&d_gsumsq[g * DD + t], tq);
        }
        __syncthreads();
    }
}

// ---------------- per-(graph,dim) norm params ----------------
__global__ void k_params(const float* __restrict__ gw, const float* __restrict__ gb,
                         const float* __restrict__ ms) {
    int i = blockIdx.x * blockDim.x + threadIdx.x;
    if (i >= GG * DD) return;
    int g = i >> 7, d = i & 127;
    float c = fmaxf((float)d_cnt[g], 1.f);
    float mean = d_gsum[i] / c;
    float m2 = d_gsumsq[i] / c;
    float m = ms[d];
    float var = m2 - m * (2.f - m) * mean * mean;
    var = fmaxf(var, 0.f);
    float rstd = rsqrtf(var + 1e-5f);
    float A = gw[d] * rstd;
    d_An[i] = A;
    d_Bn[i] = gb[d] - m * mean * A;
}

// ---------------- final: normalize + residual ----------------
__global__ void k_final(const float* __restrict__ x, const int* __restrict__ batch,
                        float* __restrict__ out, int n) {
    int i = blockIdx.x * blockDim.x + threadIdx.x;
    if (i >= n * 32) return;
    int node = i >> 5, c = i & 31;
    int g = batch[node];
    float4 f = ((const float4*)d_f)[i];
    float4 xv = ((const float4*)x)[i];
    float4 a = ((const float4*)d_An)[g * 32 + c];
    float4 b = ((const float4*)d_Bn)[g * 32 + c];
    float4 o;
    o.x = f.x * a.x + b.x + xv.x;
    o.y = f.y * a.y + b.y + xv.y;
    o.z = f.z * a.z + b.z + xv.z;
    o.w = f.w * a.w + b.w + xv.w;
    ((float4*)out)[i] = o;
}

// ---------------- launch ----------------
extern "C" void kernel_launch(void* const* d_in, const int* in_sizes, int n_in,
                              void* d_out, int out_size) {
    const float* x     = (const float*)d_in[0];
    const int*   ei    = (const int*)d_in[1];
    const int*   batch = (const int*)d_in[2];
    const float* Wl  = (const float*)d_in[4];
    const float* bl  = (const float*)d_in[5];
    const float* Wr  = (const float*)d_in[6];
    const float* gw  = (const float*)d_in[7];
    const float* gb  = (const float*)d_in[8];
    const float* msc = (const float*)d_in[9];
    float* out = (float*)d_out;

    int n = in_sizes[0] / DD;
    int e = in_sizes[1] / 2;
    int nb = (n + 255) / 256;

    k_prep<<<(n + 255) / 256, 256>>>(Wl, Wr, n);
    k_hist<<<(e + 255) / 256, 256>>>(ei, batch, e, n);
    k_scan1<<<nb, 256>>>(n);
    k_scan2<<<1, 256>>>(nb);
    k_scan3<<<nb, 256>>>(n);
    k_fill<<<(e / 4 + 255) / 256, 256>>>(ei, e);
    k_gemm<<<(n + 63) / 64, 256>>>(x, bl, batch, n);
    k_params<<<4, 256>>>(gw, gb, msc);
    k_final<<<(n * 32 + 255) / 256, 256>>>(x, batch, out, n);
}

// round 9
// speedup vs baseline: 1.8198x; 1.0195x over previous
#include <cuda_runtime.h>
#include <cuda_fp16.h>
#include <math.h>

#define NN 50000
#define EE 600000
#define DD 128
#define GG 8

// ---------------- scratch (device globals: no allocation allowed) ----------------
__device__ float d_f[NN * DD];
__device__ int   d_deg[NN];
__device__ int   d_start[NN];
__device__ int   d_cur[NN];
__device__ int   d_adj[EE];
__device__ float d_invdeg[NN];
__device__ float d_gsum[GG * DD];
__device__ float d_gsumsq[GG * DD];
__device__ int   d_cnt[GG];
__device__ int   d_bsum[256];
__device__ uint2 d_Wpk[8192];   // fp16 packed W fragments: [(op*8+c)*128 + d]*4 + q4

// ---------------- prep: zero scratch + pack weights to fp16 fragment layout ----------------
__global__ void k_prep(const float* __restrict__ Wl, const float* __restrict__ Wr, int n) {
    int i = blockIdx.x * blockDim.x + threadIdx.x;
    if (i < n) d_deg[i] = 0;
    if (i < GG * DD) { d_gsum[i] = 0.f; d_gsumsq[i] = 0.f; }
    if (i < GG) d_cnt[i] = 0;
    if (i < 8192) {
        int q4 = i & 3, d = (i >> 2) & 127, c = (i >> 9) & 7, op = i >> 12;
        const float* W = op ? Wr : Wl;
        int k0 = c * 16;
        float2 p0 = *(const float2*)(W + (size_t)d * DD + k0 + q4 * 2);
        float2 p1 = *(const float2*)(W + (size_t)d * DD + k0 + 8 + q4 * 2);
        __half2 h0 = __float22half2_rn(p0);
        __half2 h1 = __float22half2_rn(p1);
        uint2 o;
        o.x = *reinterpret_cast<unsigned*>(&h0);
        o.y = *reinterpret_cast<unsigned*>(&h1);
        d_Wpk[i] = o;
    }
}

// ---------------- histogram of dst degrees + per-graph node counts ----------------
__global__ void k_hist(const int* __restrict__ ei, const int* __restrict__ batch, int e, int n) {
    int i = blockIdx.x * blockDim.x + threadIdx.x;
    if (i < e) atomicAdd(&d_deg[ei[e + i]], 1);
    int key = (i < n) ? batch[i] : -1;
    unsigned m = __match_any_sync(0xffffffffu, key);
    int leader = __ffs(m) - 1;
    if ((int)(threadIdx.x & 31) == leader && key >= 0)
        atomicAdd(&d_cnt[key], __popc(m));
}

// ---------------- scan stage 1: per-block degree sums ----------------
__global__ void k_scan1(int n) {
    __shared__ int sm[8];
    int t = threadIdx.x, i = blockIdx.x * 256 + t;
    int lane = t & 31, w = t >> 5;
    int v = (i < n) ? d_deg[i] : 0;
#pragma unroll
    for (int off = 16; off; off >>= 1) v += __shfl_xor_sync(0xffffffffu, v, off);
    if (lane == 0) sm[w] = v;
    __syncthreads();
    if (t == 0) {
        int s = 0;
#pragma unroll
        for (int k = 0; k < 8; ++k) s += sm[k];
        d_bsum[blockIdx.x] = s;
    }
}

// ---------------- scan stage 2 (fused): block offset by masked reduce + local scan ----------------
__global__ void k_scan3(int n, int nb) {
    __shared__ int ws[8];
    __shared__ int boff_s;
    int t = threadIdx.x, i = blockIdx.x * 256 + t;
    int lane = t & 31, w = t >> 5;

    // block offset: sum of d_bsum[j] for j < blockIdx.x
    {
        int v = (t < nb && t < blockIdx.x) ? d_bsum[t] : 0;
#pragma unroll
        for (int off = 16; off; off >>= 1) v += __shfl_xor_sync(0xffffffffu, v, off);
        if (lane == 0) ws[w] = v;
        __syncthreads();
        if (t == 0) {
            int s = 0;
#pragma unroll
            for (int k = 0; k < 8; ++k) s += ws[k];
            boff_s = s;
        }
        __syncthreads();
    }

    int own = (i < n) ? d_deg[i] : 0;
    int v = own;
#pragma unroll
    for (int off = 1; off < 32; off <<= 1) {
        int u = __shfl_up_sync(0xffffffffu, v, off);
        if (lane >= off) v += u;
    }
    __syncthreads();   // ws reuse hazard
    if (lane == 31) ws[w] = v;
    __syncthreads();
    int add = 0;
#pragma unroll
    for (int k = 0; k < 8; ++k) add += (k < w) ? ws[k] : 0;
    if (i < n) {
        int excl = v + add - own + boff_s;
        d_start[i] = excl;
        d_cur[i] = excl;
        d_invdeg[i] = 1.0f / fmaxf((float)own, 1.0f);
    }
}

// ---------------- fill adjacency (4 edges per thread for ILP) ----------------
__global__ void k_fill(const int* __restrict__ ei, int e) {
    int i0 = (blockIdx.x * blockDim.x + threadIdx.x) * 4;
#pragma unroll
    for (int u = 0; u < 4; ++u) {
        int i = i0 + u;
        if (i < e) {
            int s = ei[i];
            int d = ei[e + i];
            int p = atomicAdd(&d_cur[d], 1);
            d_adj[p] = s;
        }
    }
}

// ---------------- fused gather + tensor GEMM + GELU + stats ----------------
#define MMA_F16(c, a, b0v, b1v)                                            \
    asm volatile(                                                          \
        "mma.sync.aligned.m16n8k16.row.col.f32.f16.f16.f32 "               \
        "{%0,%1,%2,%3},{%4,%5,%6,%7},{%8,%9},{%0,%1,%2,%3};\n"             \
        : "+f"(c[0]), "+f"(c[1]), "+f"(c[2]), "+f"(c[3])                   \
        : "r"(a[0]), "r"(a[1]), "r"(a[2]), "r"(a[3]), "r"(b0v), "r"(b1v))

__device__ __forceinline__ void splith(float2 v, unsigned& h, unsigned& l) {
    __half2 hv = __float22half2_rn(v);
    float2 hf = __half22float2(hv);
    __half2 lv = __float22half2_rn(make_float2(v.x - hf.x, v.y - hf.y));
    h = *reinterpret_cast<unsigned*>(&hv);
    l = *reinterpret_cast<unsigned*>(&lv);
}

#define ASTR 132

__global__ __launch_bounds__(256, 2) void k_gemm(
    const float* __restrict__ x, const float* __restrict__ bl,
    const int* __restrict__ batch, int n)
{
    __shared__ float agg_s[64 * ASTR];
    __shared__ float red_s[8][66];
    __shared__ float red_q[8][66];
    __shared__ int   bsm[64];
    __shared__ float bias_s[128];

    int t = threadIdx.x, wid = t >> 5, lane = t & 31;
    int r = lane >> 2, q4 = lane & 3;
    int wm = wid >> 1, wn = wid & 1;
    int n0 = blockIdx.x * 64;

    if (t < 64) bsm[t] = (n0 + t < n) ? batch[n0 + t] : -1;
    if (t < 128) bias_s[t] = bl[t];

    const float4* x4 = (const float4*)x;

    // ---- gather phase: warp wid gathers nodes wid*8 .. wid*8+7 into smem (scaled) ----
#pragma unroll 1
    for (int u = 0; u < 8; ++u) {
        int ln = wid * 8 + u;
        int gn = n0 + ln;
        float4 a = make_float4(0.f, 0.f, 0.f, 0.f);
        float inv = 0.f;
        if (gn < n) {
            int s0 = d_start[gn];
            int dg = d_deg[gn];
            inv = d_invdeg[gn];
#pragma unroll 4
            for (int j = 0; j < dg; ++j) {
                int s = __ldg(&d_adj[s0 + j]);
                float4 v = x4[(size_t)s * 32 + lane];
                a.x += v.x; a.y += v.y; a.z += v.z; a.w += v.w;
            }
        }
        a.x *= inv; a.y *= inv; a.z *= inv; a.w *= inv;
        *(float4*)&agg_s[ln * ASTR + lane * 4] = a;
    }
    __syncthreads();

    int row0 = n0 + wm * 16 + r;
    int row1 = row0 + 8;
    bool v0 = row0 < n, v1 = row1 < n;
    int rc0 = v0 ? row0 : 0, rc1 = v1 ? row1 : 0;
    float x0s = v0 ? 1.f : 0.f, x1s = v1 ? 1.f : 0.f;

    float acc[8][4];
#pragma unroll
    for (int nt = 0; nt < 8; ++nt)
#pragma unroll
        for (int j = 0; j < 4; ++j) acc[nt][j] = 0.f;

    // ---- chunks 0..7: A from smem (agg, pre-scaled) ----
    int ar0 = (wm * 16 + r) * ASTR;
    int ar1 = (wm * 16 + r + 8) * ASTR;
#pragma unroll
    for (int cc = 0; cc < 8; ++cc) {
        int kof = cc * 16 + q4 * 2;
        float2 c0 = *(const float2*)&agg_s[ar0 + kof];
        float2 c1 = *(const float2*)&agg_s[ar1 + kof];
        float2 c2 = *(const float2*)&agg_s[ar0 + kof + 8];
        float2 c3 = *(const float2*)&agg_s[ar1 + kof + 8];
        unsigned ah[4], al[4];
        splith(c0, ah[0], al[0]);
        splith(c1, ah[1], al[1]);
        splith(c2, ah[2], al[2]);
        splith(c3, ah[3], al[3]);
#pragma unroll
        for (int nt = 0; nt < 8; ++nt) {
            uint2 B = d_Wpk[(cc * 128 + wn * 64 + nt * 8 + r) * 4 + q4];
            MMA_F16(acc[nt], ah, B.x, B.y);
            MMA_F16(acc[nt], al, B.x, B.y);
        }
    }

    // ---- chunks 8..15: A from global x, prefetch chain ----
    float2 b0, b1, b2, b3;
    {
        int kof = q4 * 2;
        b0 = *(const float2*)(x + (size_t)rc0 * DD + kof);
        b1 = *(const float2*)(x + (size_t)rc1 * DD + kof);
        b2 = *(const float2*)(x + (size_t)rc0 * DD + kof + 8);
        b3 = *(const float2*)(x + (size_t)rc1 * DD + kof + 8);
    }
#pragma unroll
    for (int cc = 8; cc < 16; ++cc) {
        float2 c0 = b0, c1 = b1, c2 = b2, c3 = b3;
        if (cc < 15) {
            int kof = (cc - 7) * 16 + q4 * 2;
            b0 = *(const float2*)(x + (size_t)rc0 * DD + kof);
            b1 = *(const float2*)(x + (size_t)rc1 * DD + kof);
            b2 = *(const float2*)(x + (size_t)rc0 * DD + kof + 8);
            b3 = *(const float2*)(x + (size_t)rc1 * DD + kof + 8);
        }
        c0.x *= x0s; c0.y *= x0s; c2.x *= x0s; c2.y *= x0s;
        c1.x *= x1s; c1.y *= x1s; c3.x *= x1s; c3.y *= x1s;
        unsigned ah[4], al[4];
        splith(c0, ah[0], al[0]);
        splith(c1, ah[1], al[1]);
        splith(c2, ah[2], al[2]);
        splith(c3, ah[3], al[3]);
#pragma unroll
        for (int nt = 0; nt < 8; ++nt) {
            uint2 B = d_Wpk[(cc * 128 + wn * 64 + nt * 8 + r) * 4 + q4];
            MMA_F16(acc[nt], ah, B.x, B.y);
            MMA_F16(acc[nt], al, B.x, B.y);
        }
    }

    // bias + exact GELU
#pragma unroll
    for (int nt = 0; nt < 8; ++nt) {
        int d0 = wn * 64 + nt * 8 + q4 * 2;
        float bb0 = bias_s[d0], bb1 = bias_s[d0 + 1];
        acc[nt][0] += bb0; acc[nt][1] += bb1;
        acc[nt][2] += bb0; acc[nt][3] += bb1;
#pragma unroll
        for (int j = 0; j < 4; ++j) {
            float v = acc[nt][j];
            acc[nt][j] = 0.5f * v * (1.0f + erff(v * 0.70710678118654752f));
        }
    }

    // write f
#pragma unroll
    for (int nt = 0; nt < 8; ++nt) {
        int col = wn * 64 + nt * 8 + q4 * 2;
        if (v0) *(float2*)(d_f + (size_t)row0 * DD + col) = make_float2(acc[nt][0], acc[nt][1]);
        if (v1) *(float2*)(d_f + (size_t)row1 * DD + col) = make_float2(acc[nt][2], acc[nt][3]);
    }

    // per-graph sum / sumsq
    int last = min(63, n - 1 - n0);
    int glo = bsm[0], ghi = bsm[last];
    int g0r = bsm[wm * 16 + r];
    int g1r = bsm[wm * 16 + r + 8];
    for (int g = glo; g <= ghi; ++g) {
        float s[16], q[16];
#pragma unroll
        for (int i = 0; i < 16; ++i) { s[i] = 0.f; q[i] = 0.f; }
        if (g0r == g)
#pragma unroll
            for (int nt = 0; nt < 8; ++nt) {
                float a0 = acc[nt][0], a1 = acc[nt][1];
                s[nt * 2] += a0; s[nt * 2 + 1] += a1;
                q[nt * 2] += a0 * a0; q[nt * 2 + 1] += a1 * a1;
            }
        if (g1r == g)
#pragma unroll
            for (int nt = 0; nt < 8; ++nt) {
                float a2 = acc[nt][2], a3 = acc[nt][3];
                s[nt * 2] += a2; s[nt * 2 + 1] += a3;
                q[nt * 2] += a2 * a2; q[nt * 2 + 1] += a3 * a3;
            }
#pragma unroll
        for (int off = 4; off < 32; off <<= 1)
#pragma unroll
            for (int i = 0; i < 16; ++i) {
                s[i] += __shfl_xor_sync(0xffffffffu, s[i], off);
                q[i] += __shfl_xor_sync(0xffffffffu, q[i], off);
            }
        if (lane < 4)
#pragma unroll
            for (int nt = 0; nt < 8; ++nt) {
                red_s[wid][nt * 8 + lane * 2]     = s[nt * 2];
                red_s[wid][nt * 8 + lane * 2 + 1] = s[nt * 2 + 1];
                red_q[wid][nt * 8 + lane * 2]     = q[nt * 2];
                red_q[wid][nt * 8 + lane * 2 + 1] = q[nt * 2 + 1];
            }
        __syncthreads();
        if (t < 128) {
            int wn_ = t >> 6, dl = t & 63;
            float ts = 0.f, tq = 0.f;
#pragma unroll
            for (int wm_ = 0; wm_ < 4; ++wm_) {
                ts += red_s[wm_ * 2 + wn_][dl];
                tq += red_q[wm_ * 2 + wn_][dl];
            }
            atomicAdd(&d_gsum[g * DD + t], ts);
            atomicAdd(&d_gsumsq[g * DD + t], tq);
        }
        __syncthreads();
    }
}

// ---------------- final: per-block norm params (smem) + normalize + residual ----------------
// 512 threads, 128 nodes per block.
__global__ __launch_bounds__(512) void k_final(
    const float* __restrict__ x, const int* __restrict__ batch,
    const float* __restrict__ gw, const float* __restrict__ gb,
    const float* __restrict__ ms, float* __restrict__ out, int n)
{
    __shared__ float An_s[GG * DD];
    __shared__ float Bn_s[GG * DD];

    int t = threadIdx.x;
    int n0 = blockIdx.x * 128;
    int last = min(127, n - 1 - n0);
    int glo = batch[n0], ghi = batch[n0 + last];

    int np = (ghi - glo + 1) * DD;
    for (int i = t; i < np; i += 512) {
        int g = glo + (i >> 7), d = i & 127;
        int gi = g * DD + d;
        float c = fmaxf((float)d_cnt[g], 1.f);
        float mean = d_gsum[gi] / c;
        float m2 = d_gsumsq[gi] / c;
        float m = ms[d];
        float var = m2 - m * (2.f - m) * mean * mean;
        var = fmaxf(var, 0.f);
        float rstd = rsqrtf(var + 1e-5f);
        float A = gw[d] * rstd;
        An_s[gi] = A;
        Bn_s[gi] = gb[d] - m * mean * A;
    }
    __syncthreads();

#pragma unroll
    for (int p = 0; p < 8; ++p) {
        int flat = p * 512 + t;                 // 0..4095
        int nl = flat >> 5, c = flat & 31;
        int node = n0 + nl;
        if (node >= n) break;
        int g = batch[node];
        size_t i = (size_t)node * 32 + c;
        float4 f = ((const float4*)d_f)[i];
        float4 xv = ((const float4*)x)[i];
        float4 a = *(const float4*)&An_s[g * DD + c * 4];
        float4 b = *(const float4*)&Bn_s[g * DD + c * 4];
        float4 o;
        o.x = f.x * a.x + b.x + xv.x;
        o.y = f.y * a.y + b.y + xv.y;
        o.z = f.z * a.z + b.z + xv.z;
        o.w = f.w * a.w + b.w + xv.w;
        ((float4*)out)[i] = o;
    }
}

// ---------------- launch ----------------
extern "C" void kernel_launch(void* const* d_in, const int* in_sizes, int n_in,
                              void* d_out, int out_size) {
    const float* x     = (const float*)d_in[0];
    const int*   ei    = (const int*)d_in[1];
    const int*   batch = (const int*)d_in[2];
    const float* Wl  = (const float*)d_in[4];
    const float* bl  = (const float*)d_in[5];
    const float* Wr  = (const float*)d_in[6];
    const float* gw  = (const float*)d_in[7];
    const float* gb  = (const float*)d_in[8];
    const float* msc = (const float*)d_in[9];
    float* out = (float*)d_out;

    int n = in_sizes[0] / DD;
    int e = in_sizes[1] / 2;
    int nb = (n + 255) / 256;

    k_prep<<<(n + 255) / 256, 256>>>(Wl, Wr, n);
    k_hist<<<(e + 255) / 256, 256>>>(ei, batch, e, n);
    k_scan1<<<nb, 256>>>(n);
    k_scan3<<<nb, 256>>>(n, nb);
    k_fill<<<(e / 4 + 255) / 256, 256>>>(ei, e);
    k_gemm<<<(n + 63) / 64, 256>>>(x, bl, batch, n);
    k_final<<<(n + 127) / 128, 512>>>(x, batch, gw, gb, msc, out, n);
}

// round 11
// speedup vs baseline: 1.8967x; 1.0423x over previous
#include <cuda_runtime.h>
#include <cuda_fp16.h>
#include <math.h>

#define NN 50000
#define EE 600000
#define DD 128
#define GG 8

// ---------------- scratch (device globals: no allocation allowed) ----------------
__device__ float d_f[NN * DD];
__device__ int   d_deg[NN];      // zeroed by k_final at end of each run (and BSS-zero at load)
__device__ int   d_start[NN];
__device__ int   d_cur[NN];
__device__ int   d_adj[EE];
__device__ float d_invdeg[NN];
__device__ float d_gsum[GG * DD];
__device__ float d_gsumsq[GG * DD];
__device__ int   d_cnt[GG];
__device__ int   d_bsum[256];
__device__ uint2 d_Wpk[8192];   // fp16 packed W fragments: [(op*8+c)*128 + d]*4 + q4

// ---------------- hist: degree histogram + zero stats + pack weights ----------------
__global__ void k_hist(const int* __restrict__ ei,
                       const float* __restrict__ Wl, const float* __restrict__ Wr, int e) {
    int i = blockIdx.x * blockDim.x + threadIdx.x;
    if (i < e) atomicAdd(&d_deg[ei[e + i]], 1);
    if (i < GG * DD) { d_gsum[i] = 0.f; d_gsumsq[i] = 0.f; }
    if (i < GG) d_cnt[i] = 0;
    if (i < 8192) {
        int q4 = i & 3, d = (i >> 2) & 127, c = (i >> 9) & 7, op = i >> 12;
        const float* W = op ? Wr : Wl;
        int k0 = c * 16;
        float2 p0 = *(const float2*)(W + (size_t)d * DD + k0 + q4 * 2);
        float2 p1 = *(const float2*)(W + (size_t)d * DD + k0 + 8 + q4 * 2);
        __half2 h0 = __float22half2_rn(p0);
        __half2 h1 = __float22half2_rn(p1);
        uint2 o;
        o.x = *reinterpret_cast<unsigned*>(&h0);
        o.y = *reinterpret_cast<unsigned*>(&h1);
        d_Wpk[i] = o;
    }
}

// ---------------- scan stage 1: per-block degree sums ----------------
__global__ void k_scan1(int n) {
    __shared__ int sm[8];
    int t = threadIdx.x, i = blockIdx.x * 256 + t;
    int lane = t & 31, w = t >> 5;
    int v = (i < n) ? d_deg[i] : 0;
#pragma unroll
    for (int off = 16; off; off >>= 1) v += __shfl_xor_sync(0xffffffffu, v, off);
    if (lane == 0) sm[w] = v;
    __syncthreads();
    if (t == 0) {
        int s = 0;
#pragma unroll
        for (int k = 0; k < 8; ++k) s += sm[k];
        d_bsum[blockIdx.x] = s;
    }
}

// ---------------- scan stage 2: block offset by masked reduce + local scan ----------------
__global__ void k_scan3(int n, int nb) {
    __shared__ int ws[8];
    __shared__ int boff_s;
    int t = threadIdx.x, i = blockIdx.x * 256 + t;
    int lane = t & 31, w = t >> 5;

    {
        int v = (t < nb && t < blockIdx.x) ? d_bsum[t] : 0;
#pragma unroll
        for (int off = 16; off; off >>= 1) v += __shfl_xor_sync(0xffffffffu, v, off);
        if (lane == 0) ws[w] = v;
        __syncthreads();
        if (t == 0) {
            int s = 0;
#pragma unroll
            for (int k = 0; k < 8; ++k) s += ws[k];
            boff_s = s;
        }
        __syncthreads();
    }

    int own = (i < n) ? d_deg[i] : 0;
    int v = own;
#pragma unroll
    for (int off = 1; off < 32; off <<= 1) {
        int u = __shfl_up_sync(0xffffffffu, v, off);
        if (lane >= off) v += u;
    }
    __syncthreads();
    if (lane == 31) ws[w] = v;
    __syncthreads();
    int add = 0;
#pragma unroll
    for (int k = 0; k < 8; ++k) add += (k < w) ? ws[k] : 0;
    if (i < n) {
        int excl = v + add - own + boff_s;
        d_start[i] = excl;
        d_cur[i] = excl;
        d_invdeg[i] = 1.0f / fmaxf((float)own, 1.0f);
    }
}

// ---------------- fill adjacency (ILP=4) + per-graph node counts ----------------
__global__ void k_fill(const int* __restrict__ ei, const int* __restrict__ batch, int e, int n) {
    int tidg = blockIdx.x * blockDim.x + threadIdx.x;
    int i0 = tidg * 4;
#pragma unroll
    for (int u = 0; u < 4; ++u) {
        int i = i0 + u;
        if (i < e) {
            int s = ei[i];
            int d = ei[e + i];
            int p = atomicAdd(&d_cur[d], 1);
            d_adj[p] = s;
        }
    }
    int key = (tidg < n) ? batch[tidg] : -1;
    unsigned m = __match_any_sync(0xffffffffu, key);
    int leader = __ffs(m) - 1;
    if ((int)(threadIdx.x & 31) == leader && key >= 0)
        atomicAdd(&d_cnt[key], __popc(m));
}

// ---------------- fused gather + tensor GEMM + GELU + stats ----------------
#define MMA_F16(c, a, b0v, b1v)                                            \
    asm volatile(                                                          \
        "mma.sync.aligned.m16n8k16.row.col.f32.f16.f16.f32 "               \
        "{%0,%1,%2,%3},{%4,%5,%6,%7},{%8,%9},{%0,%1,%2,%3};\n"             \
        : "+f"(c[0]), "+f"(c[1]), "+f"(c[2]), "+f"(c[3])                   \
        : "r"(a[0]), "r"(a[1]), "r"(a[2]), "r"(a[3]), "r"(b0v), "r"(b1v))

__device__ __forceinline__ unsigned packh(float2 v) {
    __half2 hv = __float22half2_rn(v);
    return *reinterpret_cast<unsigned*>(&hv);
}

#define ASTR 132

__global__ __launch_bounds__(256, 2) void k_gemm(
    const float* __restrict__ x, const float* __restrict__ bl,
    const int* __restrict__ batch, int n)
{
    __shared__ float agg_s[64 * ASTR];
    __shared__ float red_s[8][66];
    __shared__ float red_q[8][66];
    __shared__ int   bsm[64];
    __shared__ float bias_s[128];

    int t = threadIdx.x, wid = t >> 5, lane = t & 31;
    int r = lane >> 2, q4 = lane & 3;
    int wm = wid >> 1, wn = wid & 1;
    int n0 = blockIdx.x * 64;

    if (t < 64) bsm[t] = (n0 + t < n) ? batch[n0 + t] : -1;
    if (t < 128) bias_s[t] = bl[t];

    const float4* x4 = (const float4*)x;

    // ---- gather phase: warp wid gathers nodes wid*8 .. wid*8+7 into smem (scaled) ----
#pragma unroll 1
    for (int u = 0; u < 8; ++u) {
        int ln = wid * 8 + u;
        int gn = n0 + ln;
        float4 a = make_float4(0.f, 0.f, 0.f, 0.f);
        float inv = 0.f;
        if (gn < n) {
            int s0 = d_start[gn];
            int dg = d_deg[gn];
            inv = d_invdeg[gn];
#pragma unroll 4
            for (int j = 0; j < dg; ++j) {
                int s = __ldg(&d_adj[s0 + j]);
                float4 v = x4[(size_t)s * 32 + lane];
                a.x += v.x; a.y += v.y; a.z += v.z; a.w += v.w;
            }
        }
        a.x *= inv; a.y *= inv; a.z *= inv; a.w *= inv;
        *(float4*)&agg_s[ln * ASTR + lane * 4] = a;
    }
    __syncthreads();

    int row0 = n0 + wm * 16 + r;
    int row1 = row0 + 8;
    bool v0 = row0 < n, v1 = row1 < n;
    int rc0 = v0 ? row0 : 0, rc1 = v1 ? row1 : 0;
    float x0s = v0 ? 1.f : 0.f, x1s = v1 ? 1.f : 0.f;

    float acc[8][4];
#pragma unroll
    for (int nt = 0; nt < 8; ++nt)
#pragma unroll
        for (int j = 0; j < 4; ++j) acc[nt][j] = 0.f;

    // ---- chunks 0..7: A from smem (agg, pre-scaled), single fp16 ----
    int ar0 = (wm * 16 + r) * ASTR;
    int ar1 = (wm * 16 + r + 8) * ASTR;
#pragma unroll
    for (int cc = 0; cc < 8; ++cc) {
        int kof = cc * 16 + q4 * 2;
        unsigned ah[4];
        ah[0] = packh(*(const float2*)&agg_s[ar0 + kof]);
        ah[1] = packh(*(const float2*)&agg_s[ar1 + kof]);
        ah[2] = packh(*(const float2*)&agg_s[ar0 + kof + 8]);
        ah[3] = packh(*(const float2*)&agg_s[ar1 + kof + 8]);
#pragma unroll
        for (int nt = 0; nt < 8; ++nt) {
            uint2 B = d_Wpk[(cc * 128 + wn * 64 + nt * 8 + r) * 4 + q4];
            MMA_F16(acc[nt], ah, B.x, B.y);
        }
    }

    // ---- chunks 8..15: A from global x, prefetch chain ----
    float2 b0, b1, b2, b3;
    {
        int kof = q4 * 2;
        b0 = *(const float2*)(x + (size_t)rc0 * DD + kof);
        b1 = *(const float2*)(x + (size_t)rc1 * DD + kof);
        b2 = *(const float2*)(x + (size_t)rc0 * DD + kof + 8);
        b3 = *(const float2*)(x + (size_t)rc1 * DD + kof + 8);
    }
#pragma unroll
    for (int cc = 8; cc < 16; ++cc) {
        float2 c0 = b0, c1 = b1, c2 = b2, c3 = b3;
        if (cc < 15) {
            int kof = (cc - 7) * 16 + q4 * 2;
            b0 = *(const float2*)(x + (size_t)rc0 * DD + kof);
            b1 = *(const float2*)(x + (size_t)rc1 * DD + kof);
            b2 = *(const float2*)(x + (size_t)rc0 * DD + kof + 8);
            b3 = *(const float2*)(x + (size_t)rc1 * DD + kof + 8);
        }
        c0.x *= x0s; c0.y *= x0s; c2.x *= x0s; c2.y *= x0s;
        c1.x *= x1s; c1.y *= x1s; c3.x *= x1s; c3.y *= x1s;
        unsigned ah[4];
        ah[0] = packh(c0);
        ah[1] = packh(c1);
        ah[2] = packh(c2);
        ah[3] = packh(c3);
#pragma unroll
        for (int nt = 0; nt < 8; ++nt) {
            uint2 B = d_Wpk[(cc * 128 + wn * 64 + nt * 8 + r) * 4 + q4];
            MMA_F16(acc[nt], ah, B.x, B.y);
        }
    }

    // bias + exact GELU
#pragma unroll
    for (int nt = 0; nt < 8; ++nt) {
        int d0 = wn * 64 + nt * 8 + q4 * 2;
        float bb0 = bias_s[d0], bb1 = bias_s[d0 + 1];
        acc[nt][0] += bb0; acc[nt][1] += bb1;
        acc[nt][2] += bb0; acc[nt][3] += bb1;
#pragma unroll
        for (int j = 0; j < 4; ++j) {
            float v = acc[nt][j];
            acc[nt][j] = 0.5f * v * (1.0f + erff(v * 0.70710678118654752f));
        }
    }

    // write f
#pragma unroll
    for (int nt = 0; nt < 8; ++nt) {
        int col = wn * 64 + nt * 8 + q4 * 2;
        if (v0) *(float2*)(d_f + (size_t)row0 * DD + col) = make_float2(acc[nt][0], acc[nt][1]);
        if (v1) *(float2*)(d_f + (size_t)row1 * DD + col) = make_float2(acc[nt][2], acc[nt][3]);
    }

    // per-graph sum / sumsq
    int last = min(63, n - 1 - n0);
    int glo = bsm[0], ghi = bsm[last];
    int g0r = bsm[wm * 16 + r];
    int g1r = bsm[wm * 16 + r + 8];
    for (int g = glo; g <= ghi; ++g) {
        float s[16], q[16];
#pragma unroll
        for (int i = 0; i < 16; ++i) { s[i] = 0.f; q[i] = 0.f; }
        if (g0r == g)
#pragma unroll
            for (int nt = 0; nt < 8; ++nt) {
                float a0 = acc[nt][0], a1 = acc[nt][1];
                s[nt * 2] += a0; s[nt * 2 + 1] += a1;
                q[nt * 2] += a0 * a0; q[nt * 2 + 1] += a1 * a1;
            }
        if (g1r == g)
#pragma unroll
            for (int nt = 0; nt < 8; ++nt) {
                float a2 = acc[nt][2], a3 = acc[nt][3];
                s[nt * 2] += a2; s[nt * 2 + 1] += a3;
                q[nt * 2] += a2 * a2; q[nt * 2 + 1] += a3 * a3;
            }
#pragma unroll
        for (int off = 4; off < 32; off <<= 1)
#pragma unroll
            for (int i = 0; i < 16; ++i) {
                s[i] += __shfl_xor_sync(0xffffffffu, s[i], off);
                q[i] += __shfl_xor_sync(0xffffffffu, q[i], off);
            }
        if (lane < 4)
#pragma unroll
            for (int nt = 0; nt < 8; ++nt) {
                red_s[wid][nt * 8 + lane * 2]     = s[nt * 2];
                red_s[wid][nt * 8 + lane * 2 + 1] = s[nt * 2 + 1];
                red_q[wid][nt * 8 + lane * 2]     = q[nt * 2];
                red_q[wid][nt * 8 + lane * 2 + 1] = q[nt * 2 + 1];
            }
        __syncthreads();
        if (t < 128) {
            int wn_ = t >> 6, dl = t & 63;
            float ts = 0.f, tq = 0.f;
#pragma unroll
            for (int wm_ = 0; wm_ < 4; ++wm_) {
                ts += red_s[wm_ * 2 + wn_][dl];
                tq += red_q[wm_ * 2 + wn_][dl];
            }
            atomicAdd(&d_gsum[g * DD + t], ts);
            atomicAdd(&d_gsumsq[g * DD + t], tq);
        }
        __syncthreads();
    }
}

// ---------------- final: per-block norm params + normalize + residual + re-zero d_deg ----------------
__global__ __launch_bounds__(512) void k_final(
    const float* __restrict__ x, const int* __restrict__ batch,
    const float* __restrict__ gw, const float* __restrict__ gb,
    const float* __restrict__ ms, float* __restrict__ out, int n)
{
    __shared__ float An_s[GG * DD];
    __shared__ float Bn_s[GG * DD];

    int t = threadIdx.x;
    int n0 = blockIdx.x * 128;
    int last = min(127, n - 1 - n0);
    int glo = batch[n0], ghi = batch[n0 + last];

    // re-zero degree counters for the next run (graph replay reuses state)
    if (t < 128 && n0 + t < n) d_deg[n0 + t] = 0;

    int np = (ghi - glo + 1) * DD;
    for (int i = t; i < np; i += 512) {
        int g = glo + (i >> 7), d = i & 127;
        int gi = g * DD + d;
        float c = fmaxf((float)d_cnt[g], 1.f);
        float mean = d_gsum[gi] / c;
        float m2 = d_gsumsq[gi] / c;
        float m = ms[d];
        float var = m2 - m * (2.f - m) * mean * mean;
        var = fmaxf(var, 0.f);
        float rstd = rsqrtf(var + 1e-5f);
        float A = gw[d] * rstd;
        An_s[gi] = A;
        Bn_s[gi] = gb[d] - m * mean * A;
    }
    __syncthreads();

#pragma unroll
    for (int p = 0; p < 8; ++p) {
        int flat = p * 512 + t;
        int nl = flat >> 5, c = flat & 31;
        int node = n0 + nl;
        if (node >= n) break;
        int g = batch[node];
        size_t i = (size_t)node * 32 + c;
        float4 f = ((const float4*)d_f)[i];
        float4 xv = ((const float4*)x)[i];
        float4 a = *(const float4*)&An_s[g * DD + c * 4];
        float4 b = *(const float4*)&Bn_s[g * DD + c * 4];
        float4 o;
        o.x = f.x * a.x + b.x + xv.x;
        o.y = f.y * a.y + b.y + xv.y;
        o.z = f.z * a.z + b.z + xv.z;
        o.w = f.w * a.w + b.w + xv.w;
        ((float4*)out)[i] = o;
    }
}

// ---------------- launch ----------------
extern "C" void kernel_launch(void* const* d_in, const int* in_sizes, int n_in,
                              void* d_out, int out_size) {
    const float* x     = (const float*)d_in[0];
    const int*   ei    = (const int*)d_in[1];
    const int*   batch = (const int*)d_in[2];
    const float* Wl  = (const float*)d_in[4];
    const float* bl  = (const float*)d_in[5];
    const float* Wr  = (const float*)d_in[6];
    const float* gw  = (const float*)d_in[7];
    const float* gb  = (const float*)d_in[8];
    const float* msc = (const float*)d_in[9];
    float* out = (float*)d_out;

    int n = in_sizes[0] / DD;
    int e = in_sizes[1] / 2;
    int nb = (n + 255) / 256;

    k_hist<<<(e + 255) / 256, 256>>>(ei, Wl, Wr, e);
    k_scan1<<<nb, 256>>>(n);
    k_scan3<<<nb, 256>>>(n, nb);
    k_fill<<<(e / 4 + 255) / 256, 256>>>(ei, batch, e, n);
    k_gemm<<<(n + 63) / 64, 256>>>(x, bl, batch, n);
    k_final<<<(n + 127) / 128, 512>>>(x, batch, gw, gb, msc, out, n);
}

// round 12
// speedup vs baseline: 1.9745x; 1.0410x over previous
#include <cuda_runtime.h>
#include <cuda_fp16.h>
#include <math.h>

#define NN 50000
#define EE 600000
#define DD 128
#define GG 8

// ---------------- scratch (device globals: no allocation allowed) ----------------
__device__ float d_f[NN * DD];
__device__ int   d_deg[NN];      // zeroed by k_final at end of each run (and BSS-zero at load)
__device__ int   d_start[NN];
__device__ int   d_cur[NN];
__device__ int   d_adj[EE];
__device__ float d_invdeg[NN];
__device__ float d_gsum[GG * DD];
__device__ float d_gsumsq[GG * DD];
__device__ int   d_cnt[GG];
__device__ int   d_bsum[256];
__device__ uint2 d_Wpk[8192];   // fp16 packed W fragments: [(op*8+c)*128 + d]*4 + q4

// ---------------- hist: degree histogram (ILP=4) + zero stats + pack weights ----------------
__global__ void k_hist(const int* __restrict__ ei,
                       const float* __restrict__ Wl, const float* __restrict__ Wr, int e) {
    int tidg = blockIdx.x * blockDim.x + threadIdx.x;
    int i0 = tidg * 4;
#pragma unroll
    for (int u = 0; u < 4; ++u) {
        int i = i0 + u;
        if (i < e) atomicAdd(&d_deg[ei[e + i]], 1);
    }
    if (tidg < GG * DD) { d_gsum[tidg] = 0.f; d_gsumsq[tidg] = 0.f; }
    if (tidg < GG) d_cnt[tidg] = 0;
    if (tidg < 8192) {
        int q4 = tidg & 3, d = (tidg >> 2) & 127, c = (tidg >> 9) & 7, op = tidg >> 12;
        const float* W = op ? Wr : Wl;
        int k0 = c * 16;
        float2 p0 = *(const float2*)(W + (size_t)d * DD + k0 + q4 * 2);
        float2 p1 = *(const float2*)(W + (size_t)d * DD + k0 + 8 + q4 * 2);
        __half2 h0 = __float22half2_rn(p0);
        __half2 h1 = __float22half2_rn(p1);
        uint2 o;
        o.x = *reinterpret_cast<unsigned*>(&h0);
        o.y = *reinterpret_cast<unsigned*>(&h1);
        d_Wpk[tidg] = o;
    }
}

// ---------------- scan stage 1: per-block degree sums ----------------
__global__ void k_scan1(int n) {
    __shared__ int sm[8];
    int t = threadIdx.x, i = blockIdx.x * 256 + t;
    int lane = t & 31, w = t >> 5;
    int v = (i < n) ? d_deg[i] : 0;
#pragma unroll
    for (int off = 16; off; off >>= 1) v += __shfl_xor_sync(0xffffffffu, v, off);
    if (lane == 0) sm[w] = v;
    __syncthreads();
    if (t == 0) {
        int s = 0;
#pragma unroll
        for (int k = 0; k < 8; ++k) s += sm[k];
        d_bsum[blockIdx.x] = s;
    }
}

// ---------------- scan stage 2: block offset by masked reduce + local scan ----------------
__global__ void k_scan3(int n, int nb) {
    __shared__ int ws[8];
    __shared__ int boff_s;
    int t = threadIdx.x, i = blockIdx.x * 256 + t;
    int lane = t & 31, w = t >> 5;

    {
        int v = (t < nb && t < blockIdx.x) ? d_bsum[t] : 0;
#pragma unroll
        for (int off = 16; off; off >>= 1) v += __shfl_xor_sync(0xffffffffu, v, off);
        if (lane == 0) ws[w] = v;
        __syncthreads();
        if (t == 0) {
            int s = 0;
#pragma unroll
            for (int k = 0; k < 8; ++k) s += ws[k];
            boff_s = s;
        }
        __syncthreads();
    }

    int own = (i < n) ? d_deg[i] : 0;
    int v = own;
#pragma unroll
    for (int off = 1; off < 32; off <<= 1) {
        int u = __shfl_up_sync(0xffffffffu, v, off);
        if (lane >= off) v += u;
    }
    __syncthreads();
    if (lane == 31) ws[w] = v;
    __syncthreads();
    int add = 0;
#pragma unroll
    for (int k = 0; k < 8; ++k) add += (k < w) ? ws[k] : 0;
    if (i < n) {
        int excl = v + add - own + boff_s;
        d_start[i] = excl;
        d_cur[i] = excl;
        d_invdeg[i] = 1.0f / fmaxf((float)own, 1.0f);
    }
}

// ---------------- fill adjacency (ILP=8) + per-graph node counts ----------------
__global__ void k_fill(const int* __restrict__ ei, const int* __restrict__ batch, int e, int n) {
    int tidg = blockIdx.x * blockDim.x + threadIdx.x;
    int i0 = tidg * 8;
#pragma unroll
    for (int u = 0; u < 8; ++u) {
        int i = i0 + u;
        if (i < e) {
            int s = ei[i];
            int d = ei[e + i];
            int p = atomicAdd(&d_cur[d], 1);
            d_adj[p] = s;
        }
    }
    int key = (tidg < n) ? batch[tidg] : -1;
    unsigned m = __match_any_sync(0xffffffffu, key);
    int leader = __ffs(m) - 1;
    if ((int)(threadIdx.x & 31) == leader && key >= 0)
        atomicAdd(&d_cnt[key], __popc(m));
}

// ---------------- fused gather + tensor GEMM + GELU + stats ----------------
#define MMA_F16(c, a, b0v, b1v)                                            \
    asm volatile(                                                          \
        "mma.sync.aligned.m16n8k16.row.col.f32.f16.f16.f32 "               \
        "{%0,%1,%2,%3},{%4,%5,%6,%7},{%8,%9},{%0,%1,%2,%3};\n"             \
        : "+f"(c[0]), "+f"(c[1]), "+f"(c[2]), "+f"(c[3])                   \
        : "r"(a[0]), "r"(a[1]), "r"(a[2]), "r"(a[3]), "r"(b0v), "r"(b1v))

__device__ __forceinline__ unsigned packh(float2 v) {
    __half2 hv = __float22half2_rn(v);
    return *reinterpret_cast<unsigned*>(&hv);
}

#define ASTR 132

__global__ __launch_bounds__(256, 2) void k_gemm(
    const float* __restrict__ x, const float* __restrict__ bl,
    const int* __restrict__ batch, int n)
{
    __shared__ float agg_s[64 * ASTR];
    __shared__ float red_s[8][66];
    __shared__ float red_q[8][66];
    __shared__ int   bsm[64];
    __shared__ float bias_s[128];

    int t = threadIdx.x, wid = t >> 5, lane = t & 31;
    int r = lane >> 2, q4 = lane & 3;
    int wm = wid >> 1, wn = wid & 1;
    int n0 = blockIdx.x * 64;

    if (t < 64) bsm[t] = (n0 + t < n) ? batch[n0 + t] : -1;
    if (t < 128) bias_s[t] = bl[t];

    const float4* x4 = (const float4*)x;

    // ---- gather phase: warp wid gathers nodes wid*8 .. wid*8+7, MLP=8, dual accumulators ----
#pragma unroll 1
    for (int u = 0; u < 8; ++u) {
        int ln = wid * 8 + u;
        int gn = n0 + ln;
        float4 a0 = make_float4(0.f, 0.f, 0.f, 0.f);
        float4 a1 = make_float4(0.f, 0.f, 0.f, 0.f);
        float inv = 0.f;
        if (gn < n) {
            int s0 = d_start[gn];
            int dg = d_deg[gn];
            inv = d_invdeg[gn];
            int j = 0;
            for (; j + 8 <= dg; j += 8) {
                int si[8];
#pragma unroll
                for (int k = 0; k < 8; ++k) si[k] = __ldg(&d_adj[s0 + j + k]);
                float4 v0 = x4[(size_t)si[0] * 32 + lane];
                float4 v1 = x4[(size_t)si[1] * 32 + lane];
                float4 v2 = x4[(size_t)si[2] * 32 + lane];
                float4 v3 = x4[(size_t)si[3] * 32 + lane];
                float4 v4 = x4[(size_t)si[4] * 32 + lane];
                float4 v5 = x4[(size_t)si[5] * 32 + lane];
                float4 v6 = x4[(size_t)si[6] * 32 + lane];
                float4 v7 = x4[(size_t)si[7] * 32 + lane];
                a0.x += v0.x; a0.y += v0.y; a0.z += v0.z; a0.w += v0.w;
                a1.x += v1.x; a1.y += v1.y; a1.z += v1.z; a1.w += v1.w;
                a0.x += v2.x; a0.y += v2.y; a0.z += v2.z; a0.w += v2.w;
                a1.x += v3.x; a1.y += v3.y; a1.z += v3.z; a1.w += v3.w;
                a0.x += v4.x; a0.y += v4.y; a0.z += v4.z; a0.w += v4.w;
                a1.x += v5.x; a1.y += v5.y; a1.z += v5.z; a1.w += v5.w;
                a0.x += v6.x; a0.y += v6.y; a0.z += v6.z; a0.w += v6.w;
                a1.x += v7.x; a1.y += v7.y; a1.z += v7.z; a1.w += v7.w;
            }
#pragma unroll 4
            for (; j < dg; ++j) {
                int s = __ldg(&d_adj[s0 + j]);
                float4 v = x4[(size_t)s * 32 + lane];
                a0.x += v.x; a0.y += v.y; a0.z += v.z; a0.w += v.w;
            }
        }
        float4 a;
        a.x = (a0.x + a1.x) * inv;
        a.y = (a0.y + a1.y) * inv;
        a.z = (a0.z + a1.z) * inv;
        a.w = (a0.w + a1.w) * inv;
        *(float4*)&agg_s[ln * ASTR + lane * 4] = a;
    }
    __syncthreads();

    int row0 = n0 + wm * 16 + r;
    int row1 = row0 + 8;
    bool v0 = row0 < n, v1 = row1 < n;
    int rc0 = v0 ? row0 : 0, rc1 = v1 ? row1 : 0;
    float x0s = v0 ? 1.f : 0.f, x1s = v1 ? 1.f : 0.f;

    float acc[8][4];
#pragma unroll
    for (int nt = 0; nt < 8; ++nt)
#pragma unroll
        for (int j = 0; j < 4; ++j) acc[nt][j] = 0.f;

    // ---- chunks 0..7: A from smem (agg, pre-scaled), single fp16 ----
    int ar0 = (wm * 16 + r) * ASTR;
    int ar1 = (wm * 16 + r + 8) * ASTR;
#pragma unroll
    for (int cc = 0; cc < 8; ++cc) {
        int kof = cc * 16 + q4 * 2;
        unsigned ah[4];
        ah[0] = packh(*(const float2*)&agg_s[ar0 + kof]);
        ah[1] = packh(*(const float2*)&agg_s[ar1 + kof]);
        ah[2] = packh(*(const float2*)&agg_s[ar0 + kof + 8]);
        ah[3] = packh(*(const float2*)&agg_s[ar1 + kof + 8]);
#pragma unroll
        for (int nt = 0; nt < 8; ++nt) {
            uint2 B = d_Wpk[(cc * 128 + wn * 64 + nt * 8 + r) * 4 + q4];
            MMA_F16(acc[nt], ah, B.x, B.y);
        }
    }

    // ---- chunks 8..15: A from global x, prefetch chain ----
    float2 b0, b1, b2, b3;
    {
        int kof = q4 * 2;
        b0 = *(const float2*)(x + (size_t)rc0 * DD + kof);
        b1 = *(const float2*)(x + (size_t)rc1 * DD + kof);
        b2 = *(const float2*)(x + (size_t)rc0 * DD + kof + 8);
        b3 = *(const float2*)(x + (size_t)rc1 * DD + kof + 8);
    }
#pragma unroll
    for (int cc = 8; cc < 16; ++cc) {
        float2 c0 = b0, c1 = b1, c2 = b2, c3 = b3;
        if (cc < 15) {
            int kof = (cc - 7) * 16 + q4 * 2;
            b0 = *(const float2*)(x + (size_t)rc0 * DD + kof);
            b1 = *(const float2*)(x + (size_t)rc1 * DD + kof);
            b2 = *(const float2*)(x + (size_t)rc0 * DD + kof + 8);
            b3 = *(const float2*)(x + (size_t)rc1 * DD + kof + 8);
        }
        c0.x *= x0s; c0.y *= x0s; c2.x *= x0s; c2.y *= x0s;
        c1.x *= x1s; c1.y *= x1s; c3.x *= x1s; c3.y *= x1s;
        unsigned ah[4];
        ah[0] = packh(c0);
        ah[1] = packh(c1);
        ah[2] = packh(c2);
        ah[3] = packh(c3);
#pragma unroll
        for (int nt = 0; nt < 8; ++nt) {
            uint2 B = d_Wpk[(cc * 128 + wn * 64 + nt * 8 + r) * 4 + q4];
            MMA_F16(acc[nt], ah, B.x, B.y);
        }
    }

    // bias + exact GELU
#pragma unroll
    for (int nt = 0; nt < 8; ++nt) {
        int d0 = wn * 64 + nt * 8 + q4 * 2;
        float bb0 = bias_s[d0], bb1 = bias_s[d0 + 1];
        acc[nt][0] += bb0; acc[nt][1] += bb1;
        acc[nt][2] += bb0; acc[nt][3] += bb1;
#pragma unroll
        for (int j = 0; j < 4; ++j) {
            float v = acc[nt][j];
            acc[nt][j] = 0.5f * v * (1.0f + erff(v * 0.70710678118654752f));
        }
    }

    // write f
#pragma unroll
    for (int nt = 0; nt < 8; ++nt) {
        int col = wn * 64 + nt * 8 + q4 * 2;
        if (v0) *(float2*)(d_f + (size_t)row0 * DD + col) = make_float2(acc[nt][0], acc[nt][1]);
        if (v1) *(float2*)(d_f + (size_t)row1 * DD + col) = make_float2(acc[nt][2], acc[nt][3]);
    }

    // per-graph sum / sumsq
    int last = min(63, n - 1 - n0);
    int glo = bsm[0], ghi = bsm[last];
    int g0r = bsm[wm * 16 + r];
    int g1r = bsm[wm * 16 + r + 8];
    for (int g = glo; g <= ghi; ++g) {
        float s[16], q[16];
#pragma unroll
        for (int i = 0; i < 16; ++i) { s[i] = 0.f; q[i] = 0.f; }
        if (g0r == g)
#pragma unroll
            for (int nt = 0; nt < 8; ++nt) {
                float a0 = acc[nt][0], a1 = acc[nt][1];
                s[nt * 2] += a0; s[nt * 2 + 1] += a1;
                q[nt * 2] += a0 * a0; q[nt * 2 + 1] += a1 * a1;
            }
        if (g1r == g)
#pragma unroll
            for (int nt = 0; nt < 8; ++nt) {
                float a2 = acc[nt][2], a3 = acc[nt][3];
                s[nt * 2] += a2; s[nt * 2 + 1] += a3;
                q[nt * 2] += a2 * a2; q[nt * 2 + 1] += a3 * a3;
            }
#pragma unroll
        for (int off = 4; off < 32; off <<= 1)
#pragma unroll
            for (int i = 0; i < 16; ++i) {
                s[i] += __shfl_xor_sync(0xffffffffu, s[i], off);
                q[i] += __shfl_xor_sync(0xffffffffu, q[i], off);
            }
        if (lane < 4)
#pragma unroll
            for (int nt = 0; nt < 8; ++nt) {
                red_s[wid][nt * 8 + lane * 2]     = s[nt * 2];
                red_s[wid][nt * 8 + lane * 2 + 1] = s[nt * 2 + 1];
                red_q[wid][nt * 8 + lane * 2]     = q[nt * 2];
                red_q[wid][nt * 8 + lane * 2 + 1] = q[nt * 2 + 1];
            }
        __syncthreads();
        if (t < 128) {
            int wn_ = t >> 6, dl = t & 63;
            float ts = 0.f, tq = 0.f;
#pragma unroll
            for (int wm_ = 0; wm_ < 4; ++wm_) {
                ts += red_s[wm_ * 2 + wn_][dl];
                tq += red_q[wm_ * 2 + wn_][dl];
            }
            atomicAdd(&d_gsum[g * DD + t], ts);
            atomicAdd(&d_gsumsq[g * DD + t], tq);
        }
        __syncthreads();
    }
}

// ---------------- final: per-block norm params + normalize + residual + re-zero d_deg ----------------
__global__ __launch_bounds__(512) void k_final(
    const float* __restrict__ x, const int* __restrict__ batch,
    const float* __restrict__ gw, const float* __restrict__ gb,
    const float* __restrict__ ms, float* __restrict__ out, int n)
{
    __shared__ float An_s[GG * DD];
    __shared__ float Bn_s[GG * DD];

    int t = threadIdx.x;
    int n0 = blockIdx.x * 128;
    int last = min(127, n - 1 - n0);
    int glo = batch[n0], ghi = batch[n0 + last];

    // re-zero degree counters for the next run (graph replay reuses state)
    if (t < 128 && n0 + t < n) d_deg[n0 + t] = 0;

    int np = (ghi - glo + 1) * DD;
    for (int i = t; i < np; i += 512) {
        int g = glo + (i >> 7), d = i & 127;
        int gi = g * DD + d;
        float c = fmaxf((float)d_cnt[g], 1.f);
        float mean = d_gsum[gi] / c;
        float m2 = d_gsumsq[gi] / c;
        float m = ms[d];
        float var = m2 - m * (2.f - m) * mean * mean;
        var = fmaxf(var, 0.f);
        float rstd = rsqrtf(var + 1e-5f);
        float A = gw[d] * rstd;
        An_s[gi] = A;
        Bn_s[gi] = gb[d] - m * mean * A;
    }
    __syncthreads();

#pragma unroll
    for (int p = 0; p < 8; ++p) {
        int flat = p * 512 + t;
        int nl = flat >> 5, c = flat & 31;
        int node = n0 + nl;
        if (node >= n) break;
        int g = batch[node];
        size_t i = (size_t)node * 32 + c;
        float4 f = ((const float4*)d_f)[i];
        float4 xv = ((const float4*)x)[i];
        float4 a = *(const float4*)&An_s[g * DD + c * 4];
        float4 b = *(const float4*)&Bn_s[g * DD + c * 4];
        float4 o;
        o.x = f.x * a.x + b.x + xv.x;
        o.y = f.y * a.y + b.y + xv.y;
        o.z = f.z * a.z + b.z + xv.z;
        o.w = f.w * a.w + b.w + xv.w;
        ((float4*)out)[i] = o;
    }
}

// ---------------- launch ----------------
extern "C" void kernel_launch(void* const* d_in, const int* in_sizes, int n_in,
                              void* d_out, int out_size) {
    const float* x     = (const float*)d_in[0];
    const int*   ei    = (const int*)d_in[1];
    const int*   batch = (const int*)d_in[2];
    const float* Wl  = (const float*)d_in[4];
    const float* bl  = (const float*)d_in[5];
    const float* Wr  = (const float*)d_in[6];
    const float* gw  = (const float*)d_in[7];
    const float* gb  = (const float*)d_in[8];
    const float* msc = (const float*)d_in[9];
    float* out = (float*)d_out;

    int n = in_sizes[0] / DD;
    int e = in_sizes[1] / 2;
    int nb = (n + 255) / 256;

    k_hist<<<(e / 4 + 255) / 256, 256>>>(ei, Wl, Wr, e);
    k_scan1<<<nb, 256>>>(n);
    k_scan3<<<nb, 256>>>(n, nb);
    k_fill<<<(e / 8 + 255) / 256, 256>>>(ei, batch, e, n);
    k_gemm<<<(n + 63) / 64, 256>>>(x, bl, batch, n);
    k_final<<<(n + 127) / 128, 512>>>(x, batch, gw, gb, msc, out, n);
}

// round 13
// speedup vs baseline: 1.9811x; 1.0033x over previous
#include <cuda_runtime.h>
#include <cuda_fp16.h>
#include <math.h>

#define NN 50000
#define EE 600000
#define DD 128
#define GG 8

// ---------------- scratch (device globals: no allocation allowed) ----------------
__device__ float d_f[NN * DD];
__device__ int   d_deg[NN];      // zeroed by k_final at end of each run (and BSS-zero at load)
__device__ int   d_start[NN];
__device__ int   d_rank[EE];     // per-edge rank within its dst segment (from hist atomic)
__device__ int   d_adj[EE];
__device__ float d_invdeg[NN];
__device__ float d_gsum[GG * DD];
__device__ float d_gsumsq[GG * DD];
__device__ int   d_cnt[GG];
__device__ int   d_bsum[256];
__device__ uint2 d_Wpk[8192];   // fp16 packed W fragments: [(op*8+c)*128 + d]*4 + q4

// ---------------- hist: degree histogram + edge ranks (ILP=4) + zero stats + pack weights ----------------
__global__ void k_hist(const int* __restrict__ ei,
                       const float* __restrict__ Wl, const float* __restrict__ Wr, int e) {
    int tidg = blockIdx.x * blockDim.x + threadIdx.x;
    int i0 = tidg * 4;
#pragma unroll
    for (int u = 0; u < 4; ++u) {
        int i = i0 + u;
        if (i < e) {
            int r = atomicAdd(&d_deg[ei[e + i]], 1);
            d_rank[i] = r;
        }
    }
    if (tidg < GG * DD) { d_gsum[tidg] = 0.f; d_gsumsq[tidg] = 0.f; }
    if (tidg < GG) d_cnt[tidg] = 0;
    if (tidg < 8192) {
        int q4 = tidg & 3, d = (tidg >> 2) & 127, c = (tidg >> 9) & 7, op = tidg >> 12;
        const float* W = op ? Wr : Wl;
        int k0 = c * 16;
        float2 p0 = *(const float2*)(W + (size_t)d * DD + k0 + q4 * 2);
        float2 p1 = *(const float2*)(W + (size_t)d * DD + k0 + 8 + q4 * 2);
        __half2 h0 = __float22half2_rn(p0);
        __half2 h1 = __float22half2_rn(p1);
        uint2 o;
        o.x = *reinterpret_cast<unsigned*>(&h0);
        o.y = *reinterpret_cast<unsigned*>(&h1);
        d_Wpk[tidg] = o;
    }
}

// ---------------- scan stage 1: per-block degree sums ----------------
__global__ void k_scan1(int n) {
    __shared__ int sm[8];
    int t = threadIdx.x, i = blockIdx.x * 256 + t;
    int lane = t & 31, w = t >> 5;
    int v = (i < n) ? d_deg[i] : 0;
#pragma unroll
    for (int off = 16; off; off >>= 1) v += __shfl_xor_sync(0xffffffffu, v, off);
    if (lane == 0) sm[w] = v;
    __syncthreads();
    if (t == 0) {
        int s = 0;
#pragma unroll
        for (int k = 0; k < 8; ++k) s += sm[k];
        d_bsum[blockIdx.x] = s;
    }
}

// ---------------- scan stage 2: block offset by masked reduce + local scan ----------------
__global__ void k_scan3(int n, int nb) {
    __shared__ int ws[8];
    __shared__ int boff_s;
    int t = threadIdx.x, i = blockIdx.x * 256 + t;
    int lane = t & 31, w = t >> 5;

    {
        int v = (t < nb && t < blockIdx.x) ? d_bsum[t] : 0;
#pragma unroll
        for (int off = 16; off; off >>= 1) v += __shfl_xor_sync(0xffffffffu, v, off);
        if (lane == 0) ws[w] = v;
        __syncthreads();
        if (t == 0) {
            int s = 0;
#pragma unroll
            for (int k = 0; k < 8; ++k) s += ws[k];
            boff_s = s;
        }
        __syncthreads();
    }

    int own = (i < n) ? d_deg[i] : 0;
    int v = own;
#pragma unroll
    for (int off = 1; off < 32; off <<= 1) {
        int u = __shfl_up_sync(0xffffffffu, v, off);
        if (lane >= off) v += u;
    }
    __syncthreads();
    if (lane == 31) ws[w] = v;
    __syncthreads();
    int add = 0;
#pragma unroll
    for (int k = 0; k < 8; ++k) add += (k < w) ? ws[k] : 0;
    if (i < n) {
        int excl = v + add - own + boff_s;
        d_start[i] = excl;
        d_invdeg[i] = 1.0f / fmaxf((float)own, 1.0f);
    }
}

// ---------------- fill adjacency: atomic-free (rank precomputed) + per-graph node counts ----------------
__global__ void k_fill(const int* __restrict__ ei, const int* __restrict__ batch, int e, int n) {
    int tidg = blockIdx.x * blockDim.x + threadIdx.x;
    int i0 = tidg * 4;
#pragma unroll
    for (int u = 0; u < 4; ++u) {
        int i = i0 + u;
        if (i < e) {
            int s = ei[i];
            int d = ei[e + i];
            int p = d_start[d] + d_rank[i];
            d_adj[p] = s;
        }
    }
    int key = (tidg < n) ? batch[tidg] : -1;
    unsigned m = __match_any_sync(0xffffffffu, key);
    int leader = __ffs(m) - 1;
    if ((int)(threadIdx.x & 31) == leader && key >= 0)
        atomicAdd(&d_cnt[key], __popc(m));
}

// ---------------- fused gather + tensor GEMM + GELU + stats ----------------
#define MMA_F16(c, a, b0v, b1v)                                            \
    asm volatile(                                                          \
        "mma.sync.aligned.m16n8k16.row.col.f32.f16.f16.f32 "               \
        "{%0,%1,%2,%3},{%4,%5,%6,%7},{%8,%9},{%0,%1,%2,%3};\n"             \
        : "+f"(c[0]), "+f"(c[1]), "+f"(c[2]), "+f"(c[3])                   \
        : "r"(a[0]), "r"(a[1]), "r"(a[2]), "r"(a[3]), "r"(b0v), "r"(b1v))

__device__ __forceinline__ unsigned packh(float2 v) {
    __half2 hv = __float22half2_rn(v);
    return *reinterpret_cast<unsigned*>(&hv);
}

#define ASTR 132

__global__ __launch_bounds__(256, 2) void k_gemm(
    const float* __restrict__ x, const float* __restrict__ bl,
    const int* __restrict__ batch, int n)
{
    __shared__ float agg_s[64 * ASTR];
    __shared__ float red_s[8][66];
    __shared__ float red_q[8][66];
    __shared__ int   bsm[64];
    __shared__ float bias_s[128];

    int t = threadIdx.x, wid = t >> 5, lane = t & 31;
    int r = lane >> 2, q4 = lane & 3;
    int wm = wid >> 1, wn = wid & 1;
    int n0 = blockIdx.x * 64;

    if (t < 64) bsm[t] = (n0 + t < n) ? batch[n0 + t] : -1;
    if (t < 128) bias_s[t] = bl[t];

    const float4* x4 = (const float4*)x;

    // ---- gather phase: warp wid gathers nodes wid*8 .. wid*8+7, MLP=8, dual accumulators ----
#pragma unroll 1
    for (int u = 0; u < 8; ++u) {
        int ln = wid * 8 + u;
        int gn = n0 + ln;
        float4 a0 = make_float4(0.f, 0.f, 0.f, 0.f);
        float4 a1 = make_float4(0.f, 0.f, 0.f, 0.f);
        float inv = 0.f;
        if (gn < n) {
            int s0 = d_start[gn];
            int dg = d_deg[gn];
            inv = d_invdeg[gn];
            int j = 0;
            for (; j + 8 <= dg; j += 8) {
                int si[8];
#pragma unroll
                for (int k = 0; k < 8; ++k) si[k] = __ldg(&d_adj[s0 + j + k]);
                float4 v0 = x4[(size_t)si[0] * 32 + lane];
                float4 v1 = x4[(size_t)si[1] * 32 + lane];
                float4 v2 = x4[(size_t)si[2] * 32 + lane];
                float4 v3 = x4[(size_t)si[3] * 32 + lane];
                float4 v4 = x4[(size_t)si[4] * 32 + lane];
                float4 v5 = x4[(size_t)si[5] * 32 + lane];
                float4 v6 = x4[(size_t)si[6] * 32 + lane];
                float4 v7 = x4[(size_t)si[7] * 32 + lane];
                a0.x += v0.x; a0.y += v0.y; a0.z += v0.z; a0.w += v0.w;
                a1.x += v1.x; a1.y += v1.y; a1.z += v1.z; a1.w += v1.w;
                a0.x += v2.x; a0.y += v2.y; a0.z += v2.z; a0.w += v2.w;
                a1.x += v3.x; a1.y += v3.y; a1.z += v3.z; a1.w += v3.w;
                a0.x += v4.x; a0.y += v4.y; a0.z += v4.z; a0.w += v4.w;
                a1.x += v5.x; a1.y += v5.y; a1.z += v5.z; a1.w += v5.w;
                a0.x += v6.x; a0.y += v6.y; a0.z += v6.z; a0.w += v6.w;
                a1.x += v7.x; a1.y += v7.y; a1.z += v7.z; a1.w += v7.w;
            }
#pragma unroll 4
            for (; j < dg; ++j) {
                int s = __ldg(&d_adj[s0 + j]);
                float4 v = x4[(size_t)s * 32 + lane];
                a0.x += v.x; a0.y += v.y; a0.z += v.z; a0.w += v.w;
            }
        }
        float4 a;
        a.x = (a0.x + a1.x) * inv;
        a.y = (a0.y + a1.y) * inv;
        a.z = (a0.z + a1.z) * inv;
        a.w = (a0.w + a1.w) * inv;
        *(float4*)&agg_s[ln * ASTR + lane * 4] = a;
    }
    __syncthreads();

    int row0 = n0 + wm * 16 + r;
    int row1 = row0 + 8;
    bool v0 = row0 < n, v1 = row1 < n;
    int rc0 = v0 ? row0 : 0, rc1 = v1 ? row1 : 0;
    float x0s = v0 ? 1.f : 0.f, x1s = v1 ? 1.f : 0.f;

    float acc[8][4];
#pragma unroll
    for (int nt = 0; nt < 8; ++nt)
#pragma unroll
        for (int j = 0; j < 4; ++j) acc[nt][j] = 0.f;

    // ---- chunks 0..7: A from smem (agg, pre-scaled), single fp16 ----
    int ar0 = (wm * 16 + r) * ASTR;
    int ar1 = (wm * 16 + r + 8) * ASTR;
#pragma unroll
    for (int cc = 0; cc < 8; ++cc) {
        int kof = cc * 16 + q4 * 2;
        unsigned ah[4];
        ah[0] = packh(*(const float2*)&agg_s[ar0 + kof]);
        ah[1] = packh(*(const float2*)&agg_s[ar1 + kof]);
        ah[2] = packh(*(const float2*)&agg_s[ar0 + kof + 8]);
        ah[3] = packh(*(const float2*)&agg_s[ar1 + kof + 8]);
#pragma unroll
        for (int nt = 0; nt < 8; ++nt) {
            uint2 B = d_Wpk[(cc * 128 + wn * 64 + nt * 8 + r) * 4 + q4];
            MMA_F16(acc[nt], ah, B.x, B.y);
        }
    }

    // ---- chunks 8..15: A from global x, prefetch chain ----
    float2 b0, b1, b2, b3;
    {
        int kof = q4 * 2;
        b0 = *(const float2*)(x + (size_t)rc0 * DD + kof);
        b1 = *(const float2*)(x + (size_t)rc1 * DD + kof);
        b2 = *(const float2*)(x + (size_t)rc0 * DD + kof + 8);
        b3 = *(const float2*)(x + (size_t)rc1 * DD + kof + 8);
    }
#pragma unroll
    for (int cc = 8; cc < 16; ++cc) {
        float2 c0 = b0, c1 = b1, c2 = b2, c3 = b3;
        if (cc < 15) {
            int kof = (cc - 7) * 16 + q4 * 2;
            b0 = *(const float2*)(x + (size_t)rc0 * DD + kof);
            b1 = *(const float2*)(x + (size_t)rc1 * DD + kof);
            b2 = *(const float2*)(x + (size_t)rc0 * DD + kof + 8);
            b3 = *(const float2*)(x + (size_t)rc1 * DD + kof + 8);
        }
        c0.x *= x0s; c0.y *= x0s; c2.x *= x0s; c2.y *= x0s;
        c1.x *= x1s; c1.y *= x1s; c3.x *= x1s; c3.y *= x1s;
        unsigned ah[4];
        ah[0] = packh(c0);
        ah[1] = packh(c1);
        ah[2] = packh(c2);
        ah[3] = packh(c3);
#pragma unroll
        for (int nt = 0; nt < 8; ++nt) {
            uint2 B = d_Wpk[(cc * 128 + wn * 64 + nt * 8 + r) * 4 + q4];
            MMA_F16(acc[nt], ah, B.x, B.y);
        }
    }

    // bias + exact GELU
#pragma unroll
    for (int nt = 0; nt < 8; ++nt) {
        int d0 = wn * 64 + nt * 8 + q4 * 2;
        float bb0 = bias_s[d0], bb1 = bias_s[d0 + 1];
        acc[nt][0] += bb0; acc[nt][1] += bb1;
        acc[nt][2] += bb0; acc[nt][3] += bb1;
#pragma unroll
        for (int j = 0; j < 4; ++j) {
            float v = acc[nt][j];
            acc[nt][j] = 0.5f * v * (1.0f + erff(v * 0.70710678118654752f));
        }
    }

    // write f
#pragma unroll
    for (int nt = 0; nt < 8; ++nt) {
        int col = wn * 64 + nt * 8 + q4 * 2;
        if (v0) *(float2*)(d_f + (size_t)row0 * DD + col) = make_float2(acc[nt][0], acc[nt][1]);
        if (v1) *(float2*)(d_f + (size_t)row1 * DD + col) = make_float2(acc[nt][2], acc[nt][3]);
    }

    // per-graph sum / sumsq
    int last = min(63, n - 1 - n0);
    int glo = bsm[0], ghi = bsm[last];
    int g0r = bsm[wm * 16 + r];
    int g1r = bsm[wm * 16 + r + 8];
    for (int g = glo; g <= ghi; ++g) {
        float s[16], q[16];
#pragma unroll
        for (int i = 0; i < 16; ++i) { s[i] = 0.f; q[i] = 0.f; }
        if (g0r == g)
#pragma unroll
            for (int nt = 0; nt < 8; ++nt) {
                float a0 = acc[nt][0], a1 = acc[nt][1];
                s[nt * 2] += a0; s[nt * 2 + 1] += a1;
                q[nt * 2] += a0 * a0; q[nt * 2 + 1] += a1 * a1;
            }
        if (g1r == g)
#pragma unroll
            for (int nt = 0; nt < 8; ++nt) {
                float a2 = acc[nt][2], a3 = acc[nt][3];
                s[nt * 2] += a2; s[nt * 2 + 1] += a3;
                q[nt * 2] += a2 * a2; q[nt * 2 + 1] += a3 * a3;
            }
#pragma unroll
        for (int off = 4; off < 32; off <<= 1)
#pragma unroll
            for (int i = 0; i < 16; ++i) {
                s[i] += __shfl_xor_sync(0xffffffffu, s[i], off);
                q[i] += __shfl_xor_sync(0xffffffffu, q[i], off);
            }
        if (lane < 4)
#pragma unroll
            for (int nt = 0; nt < 8; ++nt) {
                red_s[wid][nt * 8 + lane * 2]     = s[nt * 2];
                red_s[wid][nt * 8 + lane * 2 + 1] = s[nt * 2 + 1];
                red_q[wid][nt * 8 + lane * 2]     = q[nt * 2];
                red_q[wid][nt * 8 + lane * 2 + 1] = q[nt * 2 + 1];
            }
        __syncthreads();
        if (t < 128) {
            int wn_ = t >> 6, dl = t & 63;
            float ts = 0.f, tq = 0.f;
#pragma unroll
            for (int wm_ = 0; wm_ < 4; ++wm_) {
                ts += red_s[wm_ * 2 + wn_][dl];
                tq += red_q[wm_ * 2 + wn_][dl];
            }
            atomicAdd(&d_gsum[g * DD + t], ts);
            atomicAdd(&d_gsumsq[g * DD + t], tq);
        }
        __syncthreads();
    }
}

// ---------------- final: per-block norm params + normalize + residual + re-zero d_deg ----------------
__global__ __launch_bounds__(512) void k_final(
    const float* __restrict__ x, const int* __restrict__ batch,
    const float* __restrict__ gw, const float* __restrict__ gb,
    const float* __restrict__ ms, float* __restrict__ out, int n)
{
    __shared__ float An_s[GG * DD];
    __shared__ float Bn_s[GG * DD];

    int t = threadIdx.x;
    int n0 = blockIdx.x * 128;
    int last = min(127, n - 1 - n0);
    int glo = batch[n0], ghi = batch[n0 + last];

    // re-zero degree counters for the next run (graph replay reuses state)
    if (t < 128 && n0 + t < n) d_deg[n0 + t] = 0;

    int np = (ghi - glo + 1) * DD;
    for (int i = t; i < np; i += 512) {
        int g = glo + (i >> 7), d = i & 127;
        int gi = g * DD + d;
        float c = fmaxf((float)d_cnt[g], 1.f);
        float mean = d_gsum[gi] / c;
        float m2 = d_gsumsq[gi] / c;
        float m = ms[d];
        float var = m2 - m * (2.f - m) * mean * mean;
        var = fmaxf(var, 0.f);
        float rstd = rsqrtf(var + 1e-5f);
        float A = gw[d] * rstd;
        An_s[gi] = A;
        Bn_s[gi] = gb[d] - m * mean * A;
    }
    __syncthreads();

#pragma unroll
    for (int p = 0; p < 8; ++p) {
        int flat = p * 512 + t;
        int nl = flat >> 5, c = flat & 31;
        int node = n0 + nl;
        if (node >= n) break;
        int g = batch[node];
        size_t i = (size_t)node * 32 + c;
        float4 f = ((const float4*)d_f)[i];
        float4 xv = ((const float4*)x)[i];
        float4 a = *(const float4*)&An_s[g * DD + c * 4];
        float4 b = *(const float4*)&Bn_s[g * DD + c * 4];
        float4 o;
        o.x = f.x * a.x + b.x + xv.x;
        o.y = f.y * a.y + b.y + xv.y;
        o.z = f.z * a.z + b.z + xv.z;
        o.w = f.w * a.w + b.w + xv.w;
        ((float4*)out)[i] = o;
    }
}

// ---------------- launch ----------------
extern "C" void kernel_launch(void* const* d_in, const int* in_sizes, int n_in,
                              void* d_out, int out_size) {
    const float* x     = (const float*)d_in[0];
    const int*   ei    = (const int*)d_in[1];
    const int*   batch = (const int*)d_in[2];
    const float* Wl  = (const float*)d_in[4];
    const float* bl  = (const float*)d_in[5];
    const float* Wr  = (const float*)d_in[6];
    const float* gw  = (const float*)d_in[7];
    const float* gb  = (const float*)d_in[8];
    const float* msc = (const float*)d_in[9];
    float* out = (float*)d_out;

    int n = in_sizes[0] / DD;
    int e = in_sizes[1] / 2;
    int nb = (n + 255) / 256;

    k_hist<<<(e / 4 + 255) / 256, 256>>>(ei, Wl, Wr, e);
    k_scan1<<<nb, 256>>>(n);
    k_scan3<<<nb, 256>>>(n, nb);
    k_fill<<<(e / 4 + 255) / 256, 256>>>(ei, batch, e, n);
    k_gemm<<<(n + 63) / 64, 256>>>(x, bl, batch, n);
    k_final<<<(n + 127) / 128, 512>>>(x, batch, gw, gb, msc, out, n);
}